// round 1
// baseline (speedup 1.0000x reference)
#include <cuda_runtime.h>

#define T_    4096
#define B_    8
#define E_    1024
#define H_    8
#define D_    128
#define KP    64      // proj dim K
#define K2    128     // 2*K (phi dim)
#define CH    128     // chunk length
#define NC    32      // T / CH
#define MR    32768   // T * B rows
#define BHN   64      // B * H
#define EPSV  1e-6f

// ---------------- scratch (device globals; no allocation allowed) ----------
__device__ float g_q[33554432];     // [MR][E]  q projection
__device__ float g_k[33554432];     // [MR][E]  k projection
__device__ float g_v[33554432];     // [MR][E]  v projection
__device__ float g_pq[33554432];    // [MR][H*K2] phi(q)
__device__ float g_pk[33554432];    // [MR][H*K2] phi(k)
__device__ float g_attn[33554432];  // [MR][E]  attention output
__device__ float g_S[33554432];     // [NC][BHN][K2][D] chunk states -> exclusive prefix
__device__ float g_z[262144];       // [NC][BHN][K2]    chunk z      -> exclusive prefix

// ---------------- SGEMM: C[M,N] = A[M,Kd] * B[N,Kd]^T + bias[N] ------------
// 128x128 block tile, 16 k-tile, 256 threads, 8x8 per-thread tile, reg prefetch.
__global__ __launch_bounds__(256) void sgemm_nt_bias(
    const float* __restrict__ A, const float* __restrict__ Bm,
    const float* __restrict__ bias, float* __restrict__ C,
    int M, int N, int Kd)
{
    __shared__ float As[16][128];
    __shared__ float Bs[16][128];
    const int bm = blockIdx.y * 128;
    const int bn = blockIdx.x * 128;
    const int tid = threadIdx.x;
    const int t0 = (tid >> 4) << 3;
    const int n0 = (tid & 15) << 3;
    const int lr = tid >> 2;
    const int lc = (tid & 3) << 2;
    const float* Ap = A + (size_t)(bm + lr) * Kd + lc;
    const float* Bp = Bm + (size_t)(bn + lr) * Kd + lc;
    const size_t half = (size_t)64 * Kd;

    float4 a0 = *(const float4*)(Ap);
    float4 a1 = *(const float4*)(Ap + half);
    float4 b0 = *(const float4*)(Bp);
    float4 b1 = *(const float4*)(Bp + half);

    float acc[8][8] = {};
    for (int k0 = 0; k0 < Kd; k0 += 16) {
        As[lc+0][lr]    = a0.x; As[lc+1][lr]    = a0.y; As[lc+2][lr]    = a0.z; As[lc+3][lr]    = a0.w;
        As[lc+0][lr+64] = a1.x; As[lc+1][lr+64] = a1.y; As[lc+2][lr+64] = a1.z; As[lc+3][lr+64] = a1.w;
        Bs[lc+0][lr]    = b0.x; Bs[lc+1][lr]    = b0.y; Bs[lc+2][lr]    = b0.z; Bs[lc+3][lr]    = b0.w;
        Bs[lc+0][lr+64] = b1.x; Bs[lc+1][lr+64] = b1.y; Bs[lc+2][lr+64] = b1.z; Bs[lc+3][lr+64] = b1.w;
        __syncthreads();
        if (k0 + 16 < Kd) {
            a0 = *(const float4*)(Ap + k0 + 16);
            a1 = *(const float4*)(Ap + k0 + 16 + half);
            b0 = *(const float4*)(Bp + k0 + 16);
            b1 = *(const float4*)(Bp + k0 + 16 + half);
        }
        #pragma unroll
        for (int kk = 0; kk < 16; kk++) {
            float4 x0 = *(const float4*)&As[kk][t0];
            float4 x1 = *(const float4*)&As[kk][t0+4];
            float4 y0 = *(const float4*)&Bs[kk][n0];
            float4 y1 = *(const float4*)&Bs[kk][n0+4];
            float ar[8] = {x0.x,x0.y,x0.z,x0.w,x1.x,x1.y,x1.z,x1.w};
            float br[8] = {y0.x,y0.y,y0.z,y0.w,y1.x,y1.y,y1.z,y1.w};
            #pragma unroll
            for (int i = 0; i < 8; i++)
                #pragma unroll
                for (int j = 0; j < 8; j++)
                    acc[i][j] = fmaf(ar[i], br[j], acc[i][j]);
        }
        __syncthreads();
    }
    float bb[8];
    #pragma unroll
    for (int j = 0; j < 8; j++) bb[j] = bias[bn + n0 + j];
    #pragma unroll
    for (int i = 0; i < 8; i++) {
        float* Cp = C + (size_t)(bm + t0 + i) * N + bn + n0;
        float4 o;
        o.x = acc[i][0]+bb[0]; o.y = acc[i][1]+bb[1]; o.z = acc[i][2]+bb[2]; o.w = acc[i][3]+bb[3];
        *(float4*)Cp = o;
        o.x = acc[i][4]+bb[4]; o.y = acc[i][5]+bb[5]; o.z = acc[i][6]+bb[6]; o.w = acc[i][7]+bb[7];
        *(float4*)(Cp + 4) = o;
    }
}

// ---------------- phi: p = (u * D^-1/4) . (sigma*rm), out = [sin,cos]*K^-1/2 ----
// grid: (MR/128, H). block 256. Outputs 128 rows x 64 k per block.
__global__ __launch_bounds__(256) void phi_kernel(
    const float* __restrict__ U, const float* __restrict__ RM,
    const float* __restrict__ SIG, float* __restrict__ OUT)
{
    __shared__ float qs[32][132];   // [d][row]
    __shared__ float rs[32][64];    // [d][k]
    const int h  = blockIdx.y;
    const int m0 = blockIdx.x << 7;
    const int tid = threadIdx.x;
    const int r0 = (tid & 31) << 2;   // row base (4 rows)
    const int kb = (tid >> 5) << 3;   // k base (8 ks)
    float acc[4][8] = {};

    for (int d0 = 0; d0 < D_; d0 += 32) {
        #pragma unroll
        for (int it = 0; it < 4; it++) {
            int idx = tid + (it << 8);
            int r  = idx >> 3;
            int c4 = (idx & 7) << 2;
            float4 vq = *(const float4*)(U + (size_t)(m0 + r) * E_ + h * D_ + d0 + c4);
            qs[c4+0][r] = vq.x; qs[c4+1][r] = vq.y; qs[c4+2][r] = vq.z; qs[c4+3][r] = vq.w;
        }
        #pragma unroll
        for (int it = 0; it < 2; it++) {
            int idx = tid + (it << 8);
            int kq = idx >> 3;
            int c4 = (idx & 7) << 2;
            float4 vr = *(const float4*)(RM + ((size_t)h * KP + kq) * D_ + d0 + c4);
            const float* sg = SIG + h * D_ + d0 + c4;
            rs[c4+0][kq] = vr.x * sg[0];
            rs[c4+1][kq] = vr.y * sg[1];
            rs[c4+2][kq] = vr.z * sg[2];
            rs[c4+3][kq] = vr.w * sg[3];
        }
        __syncthreads();
        #pragma unroll
        for (int dd = 0; dd < 32; dd++) {
            float4 av = *(const float4*)&qs[dd][r0];
            float a[4] = {av.x, av.y, av.z, av.w};
            float4 b0 = *(const float4*)&rs[dd][kb];
            float4 b1 = *(const float4*)&rs[dd][kb+4];
            float br[8] = {b0.x,b0.y,b0.z,b0.w,b1.x,b1.y,b1.z,b1.w};
            #pragma unroll
            for (int i = 0; i < 4; i++)
                #pragma unroll
                for (int j = 0; j < 8; j++)
                    acc[i][j] = fmaf(a[i], br[j], acc[i][j]);
        }
        __syncthreads();
    }
    const float dscale = 0.29730177875068026f;  // 128^-0.25
    const float kscale = 0.125f;                // 64^-0.5
    #pragma unroll
    for (int i = 0; i < 4; i++) {
        size_t base = (size_t)(m0 + r0 + i) * E_ + h * K2 + kb;
        #pragma unroll
        for (int j = 0; j < 8; j++) {
            float sv, cv;
            sincosf(acc[i][j] * dscale, &sv, &cv);
            OUT[base + j]      = sv * kscale;
            OUT[base + KP + j] = cv * kscale;
        }
    }
}

// ---------------- per-chunk state: S_c[k2][d] = sum_s pk[s][k2] * v[s][d] ------
// grid: (NC, BHN). block 256.
__global__ __launch_bounds__(256) void chunk_state_kernel(
    const float* __restrict__ PK, const float* __restrict__ V, float* __restrict__ S)
{
    __shared__ float as[16][128];
    __shared__ float bs[16][128];
    const int c = blockIdx.x, bh = blockIdx.y;
    const int b = bh >> 3, h = bh & 7;
    const int tid = threadIdx.x;
    const int t0 = (tid >> 4) << 3;   // k2 base
    const int n0 = (tid & 15) << 3;   // d base
    float acc[8][8] = {};

    for (int s0 = 0; s0 < CH; s0 += 16) {
        #pragma unroll
        for (int it = 0; it < 2; it++) {
            int idx = tid + (it << 8);
            int r  = idx >> 5;
            int c4 = (idx & 31) << 2;
            size_t grow = ((size_t)(c * CH + s0 + r) * B_ + b) * E_ + h * D_;
            *(float4*)&as[r][c4] = *(const float4*)(PK + grow + c4);
            *(float4*)&bs[r][c4] = *(const float4*)(V  + grow + c4);
        }
        __syncthreads();
        #pragma unroll
        for (int ss = 0; ss < 16; ss++) {
            float4 x0 = *(const float4*)&as[ss][t0];
            float4 x1 = *(const float4*)&as[ss][t0+4];
            float4 y0 = *(const float4*)&bs[ss][n0];
            float4 y1 = *(const float4*)&bs[ss][n0+4];
            float ar[8] = {x0.x,x0.y,x0.z,x0.w,x1.x,x1.y,x1.z,x1.w};
            float br[8] = {y0.x,y0.y,y0.z,y0.w,y1.x,y1.y,y1.z,y1.w};
            #pragma unroll
            for (int i = 0; i < 8; i++)
                #pragma unroll
                for (int j = 0; j < 8; j++)
                    acc[i][j] = fmaf(ar[i], br[j], acc[i][j]);
        }
        __syncthreads();
    }
    float* Sp = S + ((size_t)c * BHN + bh) * (K2 * D_);
    #pragma unroll
    for (int i = 0; i < 8; i++) {
        float4 o;
        o.x = acc[i][0]; o.y = acc[i][1]; o.z = acc[i][2]; o.w = acc[i][3];
        *(float4*)(Sp + (size_t)(t0 + i) * D_ + n0) = o;
        o.x = acc[i][4]; o.y = acc[i][5]; o.z = acc[i][6]; o.w = acc[i][7];
        *(float4*)(Sp + (size_t)(t0 + i) * D_ + n0 + 4) = o;
    }
}

// ---------------- per-chunk z: z_c[k2] = sum_s pk[s][k2]. grid (NC,BHN) x 128 --
__global__ void chunk_z_kernel(const float* __restrict__ PK, float* __restrict__ Z)
{
    const int c = blockIdx.x, bh = blockIdx.y;
    const int b = bh >> 3, h = bh & 7;
    const int k = threadIdx.x;
    float acc = 0.f;
    for (int s = 0; s < CH; s++)
        acc += PK[((size_t)(c * CH + s) * B_ + b) * E_ + h * K2 + k];
    Z[((size_t)c * BHN + bh) * K2 + k] = acc;
}

// ---------------- exclusive prefix over chunks, in place -----------------------
__global__ void prefix_S_kernel(float* __restrict__ S)
{
    const int bh = blockIdx.x;
    const int e  = blockIdx.y * 256 + threadIdx.x;  // 0..16383
    float acc = 0.f;
    for (int c = 0; c < NC; c++) {
        size_t idx = ((size_t)c * BHN + bh) * (K2 * D_) + e;
        float t = S[idx]; S[idx] = acc; acc += t;
    }
}

__global__ void prefix_z_kernel(float* __restrict__ Z)
{
    const int bh = blockIdx.x;
    const int k  = threadIdx.x;
    float acc = 0.f;
    for (int c = 0; c < NC; c++) {
        size_t idx = ((size_t)c * BHN + bh) * K2 + k;
        float t = Z[idx]; Z[idx] = acc; acc += t;
    }
}

// ---------------- RFA output per (chunk, bh) -----------------------------------
// scores = (pq_c . pk_c^T) masked;  num = [scores|pq] @ [v ; S_prefix];
// den = [scores|pq] @ [1 ; z_prefix]; out = num / max(den, eps).
#define RFA_SMEM ((2*128*132 + 16*132) * 4)
__global__ __launch_bounds__(256) void rfa_out_kernel(
    const float* __restrict__ PQ, const float* __restrict__ PK,
    const float* __restrict__ V,  const float* __restrict__ S,
    const float* __restrict__ Z,  float* __restrict__ OUT)
{
    extern __shared__ float sm[];
    float* Qs = sm;                    // [128][132] layout [k][t]
    float* Ss = sm + 128 * 132;        // [128][132] first [k][s] (K), then [s][t] (scores)
    float* Bs = sm + 2 * 128 * 132;    // [16][132]  (col 128 = den-vector entry)

    const int c = blockIdx.x, bh = blockIdx.y;
    const int b = bh >> 3, h = bh & 7;
    const int tid = threadIdx.x;
    const int t0 = (tid >> 4) << 3;
    const int n0 = (tid & 15) << 3;

    // load Q -> Qs[k][t], K -> Ss[k][s] (transposed stores)
    #pragma unroll
    for (int it = 0; it < 16; it++) {
        int idx = tid + (it << 8);     // 0..4095
        int r  = idx >> 5;             // t or s
        int c4 = (idx & 31) << 2;      // k
        size_t grow = ((size_t)(c * CH + r) * B_ + b) * E_ + h * K2;
        float4 vq = *(const float4*)(PQ + grow + c4);
        Qs[(c4+0)*132 + r] = vq.x; Qs[(c4+1)*132 + r] = vq.y;
        Qs[(c4+2)*132 + r] = vq.z; Qs[(c4+3)*132 + r] = vq.w;
        float4 vk = *(const float4*)(PK + grow + c4);
        Ss[(c4+0)*132 + r] = vk.x; Ss[(c4+1)*132 + r] = vk.y;
        Ss[(c4+2)*132 + r] = vk.z; Ss[(c4+3)*132 + r] = vk.w;
    }
    __syncthreads();

    // scores[t][s] = sum_k Q[t][k]*K[s][k]
    float sc[8][8] = {};
    #pragma unroll
    for (int kk = 0; kk < K2; kk++) {
        float4 x0 = *(const float4*)&Qs[kk*132 + t0];
        float4 x1 = *(const float4*)&Qs[kk*132 + t0 + 4];
        float4 y0 = *(const float4*)&Ss[kk*132 + n0];
        float4 y1 = *(const float4*)&Ss[kk*132 + n0 + 4];
        float ar[8] = {x0.x,x0.y,x0.z,x0.w,x1.x,x1.y,x1.z,x1.w};
        float br[8] = {y0.x,y0.y,y0.z,y0.w,y1.x,y1.y,y1.z,y1.w};
        #pragma unroll
        for (int i = 0; i < 8; i++)
            #pragma unroll
            for (int j = 0; j < 8; j++)
                sc[i][j] = fmaf(ar[i], br[j], sc[i][j]);
    }
    __syncthreads();
    // masked transposed store: Ss[s][t]
    #pragma unroll
    for (int j = 0; j < 8; j++)
        #pragma unroll
        for (int i = 0; i < 8; i++)
            Ss[(size_t)(n0 + j) * 132 + (t0 + i)] = (n0 + j <= t0 + i) ? sc[i][j] : 0.0f;
    __syncthreads();

    // num/den GEMM over 256 reduction rows: rows 0..127 = scores/v, 128..255 = Q/Sprefix
    float acc[8][8] = {};
    float dacc[8] = {};
    const float* Sp = S + ((size_t)c * BHN + bh) * (K2 * D_);
    const float* zp = Z + ((size_t)c * BHN + bh) * K2;
    for (int kt = 0; kt < 16; kt++) {
        const int rbase = kt << 4;
        #pragma unroll
        for (int it = 0; it < 2; it++) {
            int idx = tid + (it << 8);  // 0..511
            int r  = idx >> 5;          // 0..15
            int c4 = (idx & 31) << 2;
            int rr = rbase + r;
            float4 vv;
            if (rr < 128)
                vv = *(const float4*)(V + ((size_t)(c * CH + rr) * B_ + b) * E_ + h * D_ + c4);
            else
                vv = *(const float4*)(Sp + (size_t)(rr - 128) * D_ + c4);
            *(float4*)&Bs[r * 132 + c4] = vv;
        }
        if (tid < 16) {
            int rr = rbase + tid;
            Bs[tid * 132 + 128] = (rr < 128) ? 1.0f : zp[rr - 128];
        }
        __syncthreads();
        const float* Aop = (rbase < 128) ? (Ss + (size_t)rbase * 132)
                                         : (Qs + (size_t)(rbase - 128) * 132);
        #pragma unroll
        for (int ss = 0; ss < 16; ss++) {
            const float* arow = Aop + (size_t)ss * 132;
            float4 x0 = *(const float4*)(arow + t0);
            float4 x1 = *(const float4*)(arow + t0 + 4);
            float ar[8] = {x0.x,x0.y,x0.z,x0.w,x1.x,x1.y,x1.z,x1.w};
            float4 y0 = *(const float4*)&Bs[ss * 132 + n0];
            float4 y1 = *(const float4*)&Bs[ss * 132 + n0 + 4];
            float br[8] = {y0.x,y0.y,y0.z,y0.w,y1.x,y1.y,y1.z,y1.w};
            float bv = Bs[ss * 132 + 128];
            #pragma unroll
            for (int i = 0; i < 8; i++) {
                dacc[i] = fmaf(ar[i], bv, dacc[i]);
                #pragma unroll
                for (int j = 0; j < 8; j++)
                    acc[i][j] = fmaf(ar[i], br[j], acc[i][j]);
            }
        }
        __syncthreads();
    }

    #pragma unroll
    for (int i = 0; i < 8; i++) {
        float inv = 1.0f / fmaxf(dacc[i], EPSV);
        size_t orow = ((size_t)(c * CH + t0 + i) * B_ + b) * E_ + h * D_ + n0;
        float4 o;
        o.x = acc[i][0]*inv; o.y = acc[i][1]*inv; o.z = acc[i][2]*inv; o.w = acc[i][3]*inv;
        *(float4*)(OUT + orow) = o;
        o.x = acc[i][4]*inv; o.y = acc[i][5]*inv; o.z = acc[i][6]*inv; o.w = acc[i][7]*inv;
        *(float4*)(OUT + orow + 4) = o;
    }
}

// ---------------- launcher -----------------------------------------------------
extern "C" void kernel_launch(void* const* d_in, const int* in_sizes, int n_in,
                              void* d_out, int out_size)
{
    const float* x   = (const float*)d_in[0];
    const float* rm  = (const float*)d_in[1];
    const float* Wq  = (const float*)d_in[2];
    const float* bq  = (const float*)d_in[3];
    const float* Wk  = (const float*)d_in[4];
    const float* bk  = (const float*)d_in[5];
    const float* Wv  = (const float*)d_in[6];
    const float* bv  = (const float*)d_in[7];
    const float* Wo  = (const float*)d_in[8];
    const float* bo  = (const float*)d_in[9];
    const float* sig = (const float*)d_in[10];
    float* out = (float*)d_out;

    float *q, *k, *v, *pq, *pk, *attn, *S, *z;
    cudaGetSymbolAddress((void**)&q,    g_q);
    cudaGetSymbolAddress((void**)&k,    g_k);
    cudaGetSymbolAddress((void**)&v,    g_v);
    cudaGetSymbolAddress((void**)&pq,   g_pq);
    cudaGetSymbolAddress((void**)&pk,   g_pk);
    cudaGetSymbolAddress((void**)&attn, g_attn);
    cudaGetSymbolAddress((void**)&S,    g_S);
    cudaGetSymbolAddress((void**)&z,    g_z);

    cudaFuncSetAttribute(rfa_out_kernel,
                         cudaFuncAttributeMaxDynamicSharedMemorySize, RFA_SMEM);

    dim3 gproj(E_ / 128, MR / 128);
    sgemm_nt_bias<<<gproj, 256>>>(x, Wq, bq, q, MR, E_, E_);
    sgemm_nt_bias<<<gproj, 256>>>(x, Wk, bk, k, MR, E_, E_);
    sgemm_nt_bias<<<gproj, 256>>>(x, Wv, bv, v, MR, E_, E_);

    dim3 gphi(MR / 128, H_);
    phi_kernel<<<gphi, 256>>>(q, rm, sig, pq);
    phi_kernel<<<gphi, 256>>>(k, rm, sig, pk);

    dim3 gcs(NC, BHN);
    chunk_state_kernel<<<gcs, 256>>>(pk, v, S);
    chunk_z_kernel<<<gcs, 128>>>(pk, z);

    prefix_S_kernel<<<dim3(BHN, 64), 256>>>(S);
    prefix_z_kernel<<<BHN, 128>>>(z);

    rfa_out_kernel<<<gcs, 256, RFA_SMEM>>>(pq, pk, v, S, z, attn);

    sgemm_nt_bias<<<gproj, 256>>>(attn, Wo, bo, out, MR, E_, E_);
}

// round 6
// speedup vs baseline: 1.6811x; 1.6811x over previous
#include <cuda_runtime.h>
#include <cuda_bf16.h>
#include <cuda_fp16.h>
#include <cstdint>

#define T_    4096
#define B_    8
#define E_    1024
#define H_    8
#define D_    128
#define KP    64      // proj dim K
#define K2    128     // 2*K (phi dim)
#define CH    128     // chunk length
#define NC    32      // T / CH
#define MR    32768   // T * B rows
#define BHN   64      // B * H
#define EPSV  1e-6f

// ---- x3 HMMA GEMM config ----
#define K3        3072
#define NCHUNK    48       // K3 / 64
#define NSTAGE    3
#define STAGE_B   32768    // A 16KB + B 16KB
#define GEMM_SMEM (NSTAGE * STAGE_B)   // 98304
#define WSCALE    1024.0f

// ---------------- scratch (device globals; no allocation allowed) ----------
__device__ float g_P[33554432];     // [MR][1024]  fused p-projection (q cols 0-511, k 512-1023)
__device__ float g_v[33554432];     // [MR][E]
__device__ float g_pq[33554432];    // [MR][H*K2]
__device__ float g_pk[33554432];
__device__ float g_attn[33554432];
__device__ float g_S[33554432];     // [NC][BHN][K2][D]
__device__ float g_z[262144];       // [NC][BHN][K2]
__device__ float g_M[1048576];      // [1024][1024] fused projection matrix
__device__ float g_pb[1024];        // fused projection bias
__device__ __half g_a3[100663296];  // [MR][3072] split activations (fp16 or bf16 reuse)
__device__ __half g_w3[2][3145728]; // slot0: Wv fp16x3, slot1: Wo bf16x3

// ---------------- PTX helpers ---------------------------------------------
__device__ __forceinline__ uint32_t smem_u32(const void* p) {
    uint32_t a;
    asm("{ .reg .u64 t; cvta.to.shared.u64 t, %1; cvt.u32.u64 %0, t; }"
        : "=r"(a) : "l"(p));
    return a;
}
__device__ __forceinline__ void cp16(uint32_t dst, const void* src) {
    asm volatile("cp.async.cg.shared.global [%0], [%1], 16;" :: "r"(dst), "l"(src));
}
__device__ __forceinline__ void ldm_x4(uint32_t& r0, uint32_t& r1,
                                       uint32_t& r2, uint32_t& r3, uint32_t addr) {
    asm volatile("ldmatrix.sync.aligned.m8n8.x4.shared.b16 {%0,%1,%2,%3}, [%4];"
                 : "=r"(r0), "=r"(r1), "=r"(r2), "=r"(r3) : "r"(addr));
}
__device__ __forceinline__ void mma_f16(float* c, const uint32_t* a,
                                        uint32_t b0, uint32_t b1) {
    asm volatile(
        "mma.sync.aligned.m16n8k16.row.col.f32.f16.f16.f32 "
        "{%0,%1,%2,%3}, {%4,%5,%6,%7}, {%8,%9}, {%0,%1,%2,%3};"
        : "+f"(c[0]), "+f"(c[1]), "+f"(c[2]), "+f"(c[3])
        : "r"(a[0]), "r"(a[1]), "r"(a[2]), "r"(a[3]), "r"(b0), "r"(b1));
}
__device__ __forceinline__ void mma_bf16(float* c, const uint32_t* a,
                                         uint32_t b0, uint32_t b1) {
    asm volatile(
        "mma.sync.aligned.m16n8k16.row.col.f32.bf16.bf16.f32 "
        "{%0,%1,%2,%3}, {%4,%5,%6,%7}, {%8,%9}, {%0,%1,%2,%3};"
        : "+f"(c[0]), "+f"(c[1]), "+f"(c[2]), "+f"(c[3])
        : "r"(a[0]), "r"(a[1]), "r"(a[2]), "r"(a[3]), "r"(b0), "r"(b1));
}

// ---------------- prep: M[row][e] = c * sum_d (sig*rm)[h,k,d] * W[h*128+d][e] ----
// rows 0-511: q (h*64+k), rows 512-1023: k-proj. pb[row] = same against bias vec.
__global__ __launch_bounds__(128) void prep_M(
    const float* __restrict__ rm, const float* __restrict__ sig,
    const float* __restrict__ Wq, const float* __restrict__ Wk,
    const float* __restrict__ bq, const float* __restrict__ bk,
    float* __restrict__ M, float* __restrict__ pb)
{
    const int row = blockIdx.x;       // 0..1023
    const int isK = row >> 9;
    const int h   = (row >> 6) & 7;
    const int kk  = row & 63;
    const float* W  = isK ? Wk : Wq;
    const float* bb = isK ? bk : bq;
    __shared__ float r[128];
    const int tid = threadIdx.x;
    const float c = 0.29730177875068026f;   // 128^-0.25, tau=1
    r[tid] = c * sig[h * 128 + tid] * rm[((size_t)(h * 64 + kk)) * 128 + tid];
    __syncthreads();
    for (int e = tid; e < 1024; e += 128) {
        float acc = 0.f;
        #pragma unroll 8
        for (int d = 0; d < 128; d++)
            acc = fmaf(r[d], W[(size_t)(h * 128 + d) * 1024 + e], acc);
        M[(size_t)row * 1024 + e] = acc;
    }
    if (tid == 0) {
        float acc = 0.f;
        for (int d = 0; d < 128; d++) acc = fmaf(r[d], bb[h * 128 + d], acc);
        pb[row] = acc;
    }
}

// ---------------- phi from fused P: pq/pk = [sin,cos](P)*K^-0.5 ----------------
__global__ __launch_bounds__(256) void phi_sin(
    const float* __restrict__ P, float* __restrict__ PQ, float* __restrict__ PK)
{
    size_t idx = (size_t)blockIdx.x * 256 + threadIdx.x;   // MR*512 total
    size_t m = idx >> 9;
    int j = (int)(idx & 511);
    int h = j >> 6, kk = j & 63;
    size_t ob = m * 1024 + (h << 7) + kk;
    float pv = P[m * 1024 + j];
    float s, cc;
    sincosf(pv, &s, &cc);
    PQ[ob]      = s  * 0.125f;
    PQ[ob + 64] = cc * 0.125f;
    float pv2 = P[m * 1024 + 512 + j];
    sincosf(pv2, &s, &cc);
    PK[ob]      = s  * 0.125f;
    PK[ob + 64] = cc * 0.125f;
}

// ---------------- split fp32 -> fp16 x3 concat ------------------------------
// Activations (midIsLo=1): [hi | lo | hi].  Weights (0): [hi | hi | lo].
__global__ __launch_bounds__(256) void split3h_kernel(
    const float* __restrict__ X, __half* __restrict__ O, int midIsLo, float scale)
{
    size_t idx = (size_t)blockIdx.x * 256 + threadIdx.x;
    size_t m = idx >> 8;
    int kq = (int)(idx & 255) << 2;
    float4 v = *(const float4*)(X + m * 1024 + kq);
    float f[4] = {v.x * scale, v.y * scale, v.z * scale, v.w * scale};
    __half h[4], l[4];
    #pragma unroll
    for (int i = 0; i < 4; i++) {
        h[i] = __float2half(f[i]);
        l[i] = __float2half(f[i] - __half2float(h[i]));
    }
    __half2 hp0 = __halves2half2(h[0], h[1]);
    __half2 hp1 = __halves2half2(h[2], h[3]);
    __half2 lp0 = __halves2half2(l[0], l[1]);
    __half2 lp1 = __halves2half2(l[2], l[3]);
    __half* o = O + m * K3 + kq;
    ((__half2*)o)[0] = hp0;
    ((__half2*)o)[1] = hp1;
    ((__half2*)(o + 1024))[0] = midIsLo ? lp0 : hp0;
    ((__half2*)(o + 1024))[1] = midIsLo ? lp1 : hp1;
    ((__half2*)(o + 2048))[0] = midIsLo ? hp0 : lp0;
    ((__half2*)(o + 2048))[1] = midIsLo ? hp1 : lp1;
}

// ---------------- split fp32 -> bf16 x3 concat ------------------------------
__global__ __launch_bounds__(256) void split3b_kernel(
    const float* __restrict__ X, __nv_bfloat16* __restrict__ O, int midIsLo)
{
    size_t idx = (size_t)blockIdx.x * 256 + threadIdx.x;
    size_t m = idx >> 8;
    int kq = (int)(idx & 255) << 2;
    float4 v = *(const float4*)(X + m * 1024 + kq);
    float f[4] = {v.x, v.y, v.z, v.w};
    __nv_bfloat16 h[4], l[4];
    #pragma unroll
    for (int i = 0; i < 4; i++) {
        h[i] = __float2bfloat16(f[i]);
        l[i] = __float2bfloat16(f[i] - __bfloat162float(h[i]));
    }
    __nv_bfloat162 hp0 = __halves2bfloat162(h[0], h[1]);
    __nv_bfloat162 hp1 = __halves2bfloat162(h[2], h[3]);
    __nv_bfloat162 lp0 = __halves2bfloat162(l[0], l[1]);
    __nv_bfloat162 lp1 = __halves2bfloat162(l[2], l[3]);
    __nv_bfloat16* o = O + m * K3 + kq;
    ((__nv_bfloat162*)o)[0] = hp0;
    ((__nv_bfloat162*)o)[1] = hp1;
    ((__nv_bfloat162*)(o + 1024))[0] = midIsLo ? lp0 : hp0;
    ((__nv_bfloat162*)(o + 1024))[1] = midIsLo ? lp1 : hp1;
    ((__nv_bfloat162*)(o + 2048))[0] = midIsLo ? hp0 : lp0;
    ((__nv_bfloat162*)(o + 2048))[1] = midIsLo ? hp1 : lp1;
}

// ---------------- HMMA x3 GEMM: C = (A3 . W3^T) * outScale + bias ----------
template<bool FP16>
__global__ __launch_bounds__(256) void gemm_x3_hmma(
    const void* __restrict__ A3v, const void* __restrict__ W3v,
    const float* __restrict__ bias, float* __restrict__ C, float outScale)
{
    extern __shared__ __align__(128) char smem[];
    const uint32_t sb = smem_u32(smem);
    const int tid  = threadIdx.x;
    const int lane = tid & 31;
    const int wid  = tid >> 5;
    const int m0 = blockIdx.y << 7;
    const int n0 = blockIdx.x << 7;
    const int wm = (wid >> 1) << 5;
    const int wn = (wid & 1) << 6;

    const char* Abase = (const char*)A3v + (size_t)m0 * K3 * 2;
    const char* Bbase = (const char*)W3v + (size_t)n0 * K3 * 2;

    const int lrow = tid >> 1;
    const int lc0  = (tid & 1) << 2;
    auto load_stage = [&](int chunk, int st) {
        const size_t gcol = (size_t)(chunk << 7);
        const uint32_t sa = sb + st * STAGE_B;
        #pragma unroll
        for (int c = 0; c < 4; c++) {
            int ch = lc0 + c;
            uint32_t soff = (lrow << 7) + (((ch ^ (lrow & 7))) << 4);
            cp16(sa + soff,         Abase + (size_t)lrow * 6144 + gcol + (ch << 4));
            cp16(sa + 16384 + soff, Bbase + (size_t)lrow * 6144 + gcol + (ch << 4));
        }
    };

    #pragma unroll
    for (int s = 0; s < NSTAGE; s++) {
        load_stage(s, s);
        asm volatile("cp.async.commit_group;" ::: "memory");
    }

    const int amln = wm + (lane & 15);
    const int acb  = (lane >> 4) << 4;
    const int asw  = (amln & 7) << 4;
    const int bnln = wn + (lane & 7) + ((lane & 16) >> 1);
    const int bcb  = (lane & 8) << 1;
    const int bsw  = (lane & 7) << 4;

    float acc[2][8][4] = {};

    for (int i = 0; i < NCHUNK; i++) {
        asm volatile("cp.async.wait_group %0;" :: "n"(NSTAGE - 1) : "memory");
        __syncthreads();
        const int st = i % NSTAGE;
        const uint32_t sa = sb + st * STAGE_B;
        const uint32_t sbB = sa + 16384;
        #pragma unroll
        for (int ks = 0; ks < 4; ks++) {
            uint32_t a[2][4];
            #pragma unroll
            for (int mi = 0; mi < 2; mi++) {
                uint32_t addr = sa + ((amln + (mi << 4)) << 7)
                              + (((ks << 5) + acb) ^ asw);
                ldm_x4(a[mi][0], a[mi][1], a[mi][2], a[mi][3], addr);
            }
            #pragma unroll
            for (int njp = 0; njp < 4; njp++) {
                uint32_t q0, q1, q2, q3;
                uint32_t addr = sbB + ((bnln + (njp << 4)) << 7)
                              + (((ks << 5) + bcb) ^ bsw);
                ldm_x4(q0, q1, q2, q3, addr);
                if (FP16) {
                    mma_f16(acc[0][2*njp],     a[0], q0, q1);
                    mma_f16(acc[0][2*njp + 1], a[0], q2, q3);
                    mma_f16(acc[1][2*njp],     a[1], q0, q1);
                    mma_f16(acc[1][2*njp + 1], a[1], q2, q3);
                } else {
                    mma_bf16(acc[0][2*njp],     a[0], q0, q1);
                    mma_bf16(acc[0][2*njp + 1], a[0], q2, q3);
                    mma_bf16(acc[1][2*njp],     a[1], q0, q1);
                    mma_bf16(acc[1][2*njp + 1], a[1], q2, q3);
                }
            }
        }
        __syncthreads();
        if (i + NSTAGE < NCHUNK) load_stage(i + NSTAGE, st);
        asm volatile("cp.async.commit_group;" ::: "memory");
    }

    const int rbase = m0 + wm + (lane >> 2);
    const int cbase = n0 + wn + ((lane & 3) << 1);
    #pragma unroll
    for (int mi = 0; mi < 2; mi++) {
        #pragma unroll
        for (int nj = 0; nj < 8; nj++) {
            int col = cbase + (nj << 3);
            float b0 = bias[col], b1 = bias[col + 1];
            float* p0 = C + (size_t)(rbase + (mi << 4)) * 1024 + col;
            float* p1 = p0 + 8 * 1024;
            float2 v0 = {acc[mi][nj][0] * outScale + b0, acc[mi][nj][1] * outScale + b1};
            float2 v1 = {acc[mi][nj][2] * outScale + b0, acc[mi][nj][3] * outScale + b1};
            *(float2*)p0 = v0;
            *(float2*)p1 = v1;
        }
    }
}

// ---------------- fp32 SGEMM: C[M,N] = A[M,Kd] * B[N,Kd]^T + bias[N] -------
__global__ __launch_bounds__(256) void sgemm_nt_bias(
    const float* __restrict__ A, const float* __restrict__ Bm,
    const float* __restrict__ bias, float* __restrict__ C,
    int M, int N, int Kd)
{
    __shared__ float As[16][128];
    __shared__ float Bs[16][128];
    const int bm = blockIdx.y * 128;
    const int bn = blockIdx.x * 128;
    const int tid = threadIdx.x;
    const int t0 = (tid >> 4) << 3;
    const int n0 = (tid & 15) << 3;
    const int lr = tid >> 2;
    const int lc = (tid & 3) << 2;
    const float* Ap = A + (size_t)(bm + lr) * Kd + lc;
    const float* Bp = Bm + (size_t)(bn + lr) * Kd + lc;
    const size_t half = (size_t)64 * Kd;

    float4 a0 = *(const float4*)(Ap);
    float4 a1 = *(const float4*)(Ap + half);
    float4 b0 = *(const float4*)(Bp);
    float4 b1 = *(const float4*)(Bp + half);

    float acc[8][8] = {};
    for (int k0 = 0; k0 < Kd; k0 += 16) {
        As[lc+0][lr]    = a0.x; As[lc+1][lr]    = a0.y; As[lc+2][lr]    = a0.z; As[lc+3][lr]    = a0.w;
        As[lc+0][lr+64] = a1.x; As[lc+1][lr+64] = a1.y; As[lc+2][lr+64] = a1.z; As[lc+3][lr+64] = a1.w;
        Bs[lc+0][lr]    = b0.x; Bs[lc+1][lr]    = b0.y; Bs[lc+2][lr]    = b0.z; Bs[lc+3][lr]    = b0.w;
        Bs[lc+0][lr+64] = b1.x; Bs[lc+1][lr+64] = b1.y; Bs[lc+2][lr+64] = b1.z; Bs[lc+3][lr+64] = b1.w;
        __syncthreads();
        if (k0 + 16 < Kd) {
            a0 = *(const float4*)(Ap + k0 + 16);
            a1 = *(const float4*)(Ap + k0 + 16 + half);
            b0 = *(const float4*)(Bp + k0 + 16);
            b1 = *(const float4*)(Bp + k0 + 16 + half);
        }
        #pragma unroll
        for (int kk = 0; kk < 16; kk++) {
            float4 x0 = *(const float4*)&As[kk][t0];
            float4 x1 = *(const float4*)&As[kk][t0+4];
            float4 y0 = *(const float4*)&Bs[kk][n0];
            float4 y1 = *(const float4*)&Bs[kk][n0+4];
            float ar[8] = {x0.x,x0.y,x0.z,x0.w,x1.x,x1.y,x1.z,x1.w};
            float br[8] = {y0.x,y0.y,y0.z,y0.w,y1.x,y1.y,y1.z,y1.w};
            #pragma unroll
            for (int i = 0; i < 8; i++)
                #pragma unroll
                for (int j = 0; j < 8; j++)
                    acc[i][j] = fmaf(ar[i], br[j], acc[i][j]);
        }
        __syncthreads();
    }
    float bb[8];
    #pragma unroll
    for (int j = 0; j < 8; j++) bb[j] = bias[bn + n0 + j];
    #pragma unroll
    for (int i = 0; i < 8; i++) {
        float* Cp = C + (size_t)(bm + t0 + i) * N + bn + n0;
        float4 o;
        o.x = acc[i][0]+bb[0]; o.y = acc[i][1]+bb[1]; o.z = acc[i][2]+bb[2]; o.w = acc[i][3]+bb[3];
        *(float4*)Cp = o;
        o.x = acc[i][4]+bb[4]; o.y = acc[i][5]+bb[5]; o.z = acc[i][6]+bb[6]; o.w = acc[i][7]+bb[7];
        *(float4*)(Cp + 4) = o;
    }
}

// ---------------- per-chunk state: S_c[k2][d] = sum_s pk[s][k2] * v[s][d] ------
__global__ __launch_bounds__(256) void chunk_state_kernel(
    const float* __restrict__ PK, const float* __restrict__ V, float* __restrict__ S)
{
    __shared__ float as[16][128];
    __shared__ float bs[16][128];
    const int c = blockIdx.x, bh = blockIdx.y;
    const int b = bh >> 3, h = bh & 7;
    const int tid = threadIdx.x;
    const int t0 = (tid >> 4) << 3;
    const int n0 = (tid & 15) << 3;
    float acc[8][8] = {};

    for (int s0 = 0; s0 < CH; s0 += 16) {
        #pragma unroll
        for (int it = 0; it < 2; it++) {
            int idx = tid + (it << 8);
            int r  = idx >> 5;
            int c4 = (idx & 31) << 2;
            size_t grow = ((size_t)(c * CH + s0 + r) * B_ + b) * E_ + h * D_;
            *(float4*)&as[r][c4] = *(const float4*)(PK + grow + c4);
            *(float4*)&bs[r][c4] = *(const float4*)(V  + grow + c4);
        }
        __syncthreads();
        #pragma unroll
        for (int ss = 0; ss < 16; ss++) {
            float4 x0 = *(const float4*)&as[ss][t0];
            float4 x1 = *(const float4*)&as[ss][t0+4];
            float4 y0 = *(const float4*)&bs[ss][n0];
            float4 y1 = *(const float4*)&bs[ss][n0+4];
            float ar[8] = {x0.x,x0.y,x0.z,x0.w,x1.x,x1.y,x1.z,x1.w};
            float br[8] = {y0.x,y0.y,y0.z,y0.w,y1.x,y1.y,y1.z,y1.w};
            #pragma unroll
            for (int i = 0; i < 8; i++)
                #pragma unroll
                for (int j = 0; j < 8; j++)
                    acc[i][j] = fmaf(ar[i], br[j], acc[i][j]);
        }
        __syncthreads();
    }
    float* Sp = S + ((size_t)c * BHN + bh) * (K2 * D_);
    #pragma unroll
    for (int i = 0; i < 8; i++) {
        float4 o;
        o.x = acc[i][0]; o.y = acc[i][1]; o.z = acc[i][2]; o.w = acc[i][3];
        *(float4*)(Sp + (size_t)(t0 + i) * D_ + n0) = o;
        o.x = acc[i][4]; o.y = acc[i][5]; o.z = acc[i][6]; o.w = acc[i][7];
        *(float4*)(Sp + (size_t)(t0 + i) * D_ + n0 + 4) = o;
    }
}

__global__ void chunk_z_kernel(const float* __restrict__ PK, float* __restrict__ Z)
{
    const int c = blockIdx.x, bh = blockIdx.y;
    const int b = bh >> 3, h = bh & 7;
    const int k = threadIdx.x;
    float acc = 0.f;
    for (int s = 0; s < CH; s++)
        acc += PK[((size_t)(c * CH + s) * B_ + b) * E_ + h * K2 + k];
    Z[((size_t)c * BHN + bh) * K2 + k] = acc;
}

__global__ void prefix_S_kernel(float* __restrict__ S)
{
    const int bh = blockIdx.x;
    const int e  = blockIdx.y * 256 + threadIdx.x;
    float acc = 0.f;
    for (int c = 0; c < NC; c++) {
        size_t idx = ((size_t)c * BHN + bh) * (K2 * D_) + e;
        float t = S[idx]; S[idx] = acc; acc += t;
    }
}

__global__ void prefix_z_kernel(float* __restrict__ Z)
{
    const int bh = blockIdx.x;
    const int k  = threadIdx.x;
    float acc = 0.f;
    for (int c = 0; c < NC; c++) {
        size_t idx = ((size_t)c * BHN + bh) * K2 + k;
        float t = Z[idx]; Z[idx] = acc; acc += t;
    }
}

// ---------------- RFA output per (chunk, bh) -----------------------------------
#define RFA_SMEM ((2*128*132 + 16*132) * 4)
__global__ __launch_bounds__(256) void rfa_out_kernel(
    const float* __restrict__ PQ, const float* __restrict__ PK,
    const float* __restrict__ V,  const float* __restrict__ S,
    const float* __restrict__ Z,  float* __restrict__ OUT)
{
    extern __shared__ float sm[];
    float* Qs = sm;
    float* Ss = sm + 128 * 132;
    float* Bs = sm + 2 * 128 * 132;

    const int c = blockIdx.x, bh = blockIdx.y;
    const int b = bh >> 3, h = bh & 7;
    const int tid = threadIdx.x;
    const int t0 = (tid >> 4) << 3;
    const int n0 = (tid & 15) << 3;

    #pragma unroll
    for (int it = 0; it < 16; it++) {
        int idx = tid + (it << 8);
        int r  = idx >> 5;
        int c4 = (idx & 31) << 2;
        size_t grow = ((size_t)(c * CH + r) * B_ + b) * E_ + h * K2;
        float4 vq = *(const float4*)(PQ + grow + c4);
        Qs[(c4+0)*132 + r] = vq.x; Qs[(c4+1)*132 + r] = vq.y;
        Qs[(c4+2)*132 + r] = vq.z; Qs[(c4+3)*132 + r] = vq.w;
        float4 vk = *(const float4*)(PK + grow + c4);
        Ss[(c4+0)*132 + r] = vk.x; Ss[(c4+1)*132 + r] = vk.y;
        Ss[(c4+2)*132 + r] = vk.z; Ss[(c4+3)*132 + r] = vk.w;
    }
    __syncthreads();

    float sc[8][8] = {};
    #pragma unroll
    for (int kk = 0; kk < K2; kk++) {
        float4 x0 = *(const float4*)&Qs[kk*132 + t0];
        float4 x1 = *(const float4*)&Qs[kk*132 + t0 + 4];
        float4 y0 = *(const float4*)&Ss[kk*132 + n0];
        float4 y1 = *(const float4*)&Ss[kk*132 + n0 + 4];
        float ar[8] = {x0.x,x0.y,x0.z,x0.w,x1.x,x1.y,x1.z,x1.w};
        float br[8] = {y0.x,y0.y,y0.z,y0.w,y1.x,y1.y,y1.z,y1.w};
        #pragma unroll
        for (int i = 0; i < 8; i++)
            #pragma unroll
            for (int j = 0; j < 8; j++)
                sc[i][j] = fmaf(ar[i], br[j], sc[i][j]);
    }
    __syncthreads();
    #pragma unroll
    for (int j = 0; j < 8; j++)
        #pragma unroll
        for (int i = 0; i < 8; i++)
            Ss[(size_t)(n0 + j) * 132 + (t0 + i)] = (n0 + j <= t0 + i) ? sc[i][j] : 0.0f;
    __syncthreads();

    float acc[8][8] = {};
    float dacc[8] = {};
    const float* Sp = S + ((size_t)c * BHN + bh) * (K2 * D_);
    const float* zp = Z + ((size_t)c * BHN + bh) * K2;
    for (int kt = 0; kt < 16; kt++) {
        const int rbase = kt << 4;
        #pragma unroll
        for (int it = 0; it < 2; it++) {
            int idx = tid + (it << 8);
            int r  = idx >> 5;
            int c4 = (idx & 31) << 2;
            int rr = rbase + r;
            float4 vv;
            if (rr < 128)
                vv = *(const float4*)(V + ((size_t)(c * CH + rr) * B_ + b) * E_ + h * D_ + c4);
            else
                vv = *(const float4*)(Sp + (size_t)(rr - 128) * D_ + c4);
            *(float4*)&Bs[r * 132 + c4] = vv;
        }
        if (tid < 16) {
            int rr = rbase + tid;
            Bs[tid * 132 + 128] = (rr < 128) ? 1.0f : zp[rr - 128];
        }
        __syncthreads();
        const float* Aop = (rbase < 128) ? (Ss + (size_t)rbase * 132)
                                         : (Qs + (size_t)(rbase - 128) * 132);
        #pragma unroll
        for (int ss = 0; ss < 16; ss++) {
            const float* arow = Aop + (size_t)ss * 132;
            float4 x0 = *(const float4*)(arow + t0);
            float4 x1 = *(const float4*)(arow + t0 + 4);
            float ar[8] = {x0.x,x0.y,x0.z,x0.w,x1.x,x1.y,x1.z,x1.w};
            float4 y0 = *(const float4*)&Bs[ss * 132 + n0];
            float4 y1 = *(const float4*)&Bs[ss * 132 + n0 + 4];
            float br[8] = {y0.x,y0.y,y0.z,y0.w,y1.x,y1.y,y1.z,y1.w};
            float bv = Bs[ss * 132 + 128];
            #pragma unroll
            for (int i = 0; i < 8; i++) {
                dacc[i] = fmaf(ar[i], bv, dacc[i]);
                #pragma unroll
                for (int j = 0; j < 8; j++)
                    acc[i][j] = fmaf(ar[i], br[j], acc[i][j]);
            }
        }
        __syncthreads();
    }

    #pragma unroll
    for (int i = 0; i < 8; i++) {
        float inv = 1.0f / fmaxf(dacc[i], EPSV);
        size_t orow = ((size_t)(c * CH + t0 + i) * B_ + b) * E_ + h * D_ + n0;
        float4 o;
        o.x = acc[i][0]*inv; o.y = acc[i][1]*inv; o.z = acc[i][2]*inv; o.w = acc[i][3]*inv;
        *(float4*)(OUT + orow) = o;
        o.x = acc[i][4]*inv; o.y = acc[i][5]*inv; o.z = acc[i][6]*inv; o.w = acc[i][7]*inv;
        *(float4*)(OUT + orow + 4) = o;
    }
}

// ---------------- launcher -----------------------------------------------------
extern "C" void kernel_launch(void* const* d_in, const int* in_sizes, int n_in,
                              void* d_out, int out_size)
{
    const float* x   = (const float*)d_in[0];
    const float* rm  = (const float*)d_in[1];
    const float* Wq  = (const float*)d_in[2];
    const float* bq  = (const float*)d_in[3];
    const float* Wk  = (const float*)d_in[4];
    const float* bk  = (const float*)d_in[5];
    const float* Wv  = (const float*)d_in[6];
    const float* bv  = (const float*)d_in[7];
    const float* Wo  = (const float*)d_in[8];
    const float* bo  = (const float*)d_in[9];
    const float* sig = (const float*)d_in[10];
    float* out = (float*)d_out;

    float *P, *v, *pq, *pk, *attn, *S, *z, *M, *pb;
    __half *a3, *w3;
    cudaGetSymbolAddress((void**)&P,    g_P);
    cudaGetSymbolAddress((void**)&v,    g_v);
    cudaGetSymbolAddress((void**)&pq,   g_pq);
    cudaGetSymbolAddress((void**)&pk,   g_pk);
    cudaGetSymbolAddress((void**)&attn, g_attn);
    cudaGetSymbolAddress((void**)&S,    g_S);
    cudaGetSymbolAddress((void**)&z,    g_z);
    cudaGetSymbolAddress((void**)&M,    g_M);
    cudaGetSymbolAddress((void**)&pb,   g_pb);
    cudaGetSymbolAddress((void**)&a3,   g_a3);
    cudaGetSymbolAddress((void**)&w3,   g_w3);

    cudaFuncSetAttribute(rfa_out_kernel,
                         cudaFuncAttributeMaxDynamicSharedMemorySize, RFA_SMEM);
    cudaFuncSetAttribute(gemm_x3_hmma<true>,
                         cudaFuncAttributeMaxDynamicSharedMemorySize, GEMM_SMEM);
    cudaFuncSetAttribute(gemm_x3_hmma<false>,
                         cudaFuncAttributeMaxDynamicSharedMemorySize, GEMM_SMEM);

    const size_t WSTRIDE = 3145728;
    const float invW = 1.0f / WSCALE;
    dim3 ghmma(E_ / 128, MR / 128);

    // 1) fused q/k projection matrix: M = c*(sigma*rm) @ W per head, + bias vec
    prep_M<<<1024, 128>>>(rm, sig, Wq, Wk, bq, bk, M, pb);

    // 2) splits: x -> fp16x3 (for v), Wv -> fp16x3 (x1024), Wo -> bf16x3
    split3h_kernel<<<MR, 256>>>(x, a3, 1, 1.0f);
    split3h_kernel<<<1024, 256>>>(Wv, w3 + 0 * WSTRIDE, 0, WSCALE);
    split3b_kernel<<<1024, 256>>>(Wo, (__nv_bfloat16*)(w3 + 1 * WSTRIDE), 0);

    // 3) den-critical fused p-projection in fp32: P = x @ M^T + pb
    sgemm_nt_bias<<<dim3(E_ / 128, MR / 128), 256>>>(x, M, pb, P, MR, 1024, 1024);

    // 4) v projection: fp16x3 HMMA (num-only path)
    gemm_x3_hmma<true><<<ghmma, 256, GEMM_SMEM>>>(a3, w3 + 0 * WSTRIDE, bv, v, invW);

    // 5) phi = [sin,cos](P) * K^-0.5
    phi_sin<<<MR * 2, 256>>>(P, pq, pk);

    // 6) chunked linear-attention recurrence
    dim3 gcs(NC, BHN);
    chunk_state_kernel<<<gcs, 256>>>(pk, v, S);
    chunk_z_kernel<<<gcs, 128>>>(pk, z);
    prefix_S_kernel<<<dim3(BHN, 64), 256>>>(S);
    prefix_z_kernel<<<BHN, 128>>>(z);
    rfa_out_kernel<<<gcs, 256, RFA_SMEM>>>(pq, pk, v, S, z, attn);

    // 7) O projection: bf16x3 HMMA (measured-safe at ~6e-6 in rounds 4/5)
    split3b_kernel<<<MR, 256>>>(attn, (__nv_bfloat16*)a3, 1);
    gemm_x3_hmma<false><<<ghmma, 256, GEMM_SMEM>>>(a3, w3 + 1 * WSTRIDE, bo, out, 1.0f);
}

// round 9
// speedup vs baseline: 1.7173x; 1.0215x over previous
#include <cuda_runtime.h>
#include <cuda_bf16.h>
#include <cuda_fp16.h>
#include <cstdint>

#define T_    4096
#define B_    8
#define E_    1024
#define H_    8
#define D_    128
#define KP    64
#define K2    128
#define CH    128
#define NC    32
#define MR    32768
#define BHN   64
#define EPSV  1e-6f

#define K3        3072
#define NSTAGE    3
#define STAGE_B   32768
#define GEMM_SMEM (NSTAGE * STAGE_B)   // 96KB
#define WSCALE    1024.0f

// ---------------- scratch ---------------------------------------------------
__device__ float g_P[33554432];      // [MR][1024] fused p (q 0-511, k 512-1023)
__device__ float g_v[33554432];
__device__ float g_pq[33554432];
__device__ float g_pk[33554432];
__device__ float g_S[33554432];
__device__ float g_z[262144];
__device__ float g_M[1048576];       // fused q/k projection matrix
__device__ float g_pb[1024];
__device__ __half g_a3[100663296];   // [MR][3072] x fp16x3, later attn bf16x3 (reuse)
__device__ __half g_wv3[3145728];    // Wv fp16x3
__device__ __half g_wo3[3145728];    // Wo bf16x3 (bits in half storage)

// ---------------- PTX helpers -----------------------------------------------
__device__ __forceinline__ uint32_t smem_u32(const void* p) {
    uint32_t a;
    asm("{ .reg .u64 t; cvta.to.shared.u64 t, %1; cvt.u32.u64 %0, t; }"
        : "=r"(a) : "l"(p));
    return a;
}
__device__ __forceinline__ void cp16(uint32_t dst, const void* src) {
    asm volatile("cp.async.cg.shared.global [%0], [%1], 16;" :: "r"(dst), "l"(src));
}
__device__ __forceinline__ void ldm_x4(uint32_t& r0, uint32_t& r1,
                                       uint32_t& r2, uint32_t& r3, uint32_t addr) {
    asm volatile("ldmatrix.sync.aligned.m8n8.x4.shared.b16 {%0,%1,%2,%3}, [%4];"
                 : "=r"(r0), "=r"(r1), "=r"(r2), "=r"(r3) : "r"(addr));
}
__device__ __forceinline__ void mma_f16(float* c, const uint32_t* a,
                                        uint32_t b0, uint32_t b1) {
    asm volatile(
        "mma.sync.aligned.m16n8k16.row.col.f32.f16.f16.f32 "
        "{%0,%1,%2,%3}, {%4,%5,%6,%7}, {%8,%9}, {%0,%1,%2,%3};"
        : "+f"(c[0]), "+f"(c[1]), "+f"(c[2]), "+f"(c[3])
        : "r"(a[0]), "r"(a[1]), "r"(a[2]), "r"(a[3]), "r"(b0), "r"(b1));
}
__device__ __forceinline__ void mma_bf16(float* c, const uint32_t* a,
                                         uint32_t b0, uint32_t b1) {
    asm volatile(
        "mma.sync.aligned.m16n8k16.row.col.f32.bf16.bf16.f32 "
        "{%0,%1,%2,%3}, {%4,%5,%6,%7}, {%8,%9}, {%0,%1,%2,%3};"
        : "+f"(c[0]), "+f"(c[1]), "+f"(c[2]), "+f"(c[3])
        : "r"(a[0]), "r"(a[1]), "r"(a[2]), "r"(a[3]), "r"(b0), "r"(b1));
}

// ---------------- prep: fused q/k projection matrix + bias -------------------
__global__ __launch_bounds__(128) void prep_M(
    const float* __restrict__ rm, const float* __restrict__ sig,
    const float* __restrict__ Wq, const float* __restrict__ Wk,
    const float* __restrict__ bq, const float* __restrict__ bk,
    float* __restrict__ M, float* __restrict__ pb)
{
    const int row = blockIdx.x;
    const int isK = row >> 9;
    const int h   = (row >> 6) & 7;
    const int kk  = row & 63;
    const float* W  = isK ? Wk : Wq;
    const float* bb = isK ? bk : bq;
    __shared__ float r[128];
    const int tid = threadIdx.x;
    const float c = 0.29730177875068026f;
    r[tid] = c * sig[h * 128 + tid] * rm[((size_t)(h * 64 + kk)) * 128 + tid];
    __syncthreads();
    for (int e = tid; e < 1024; e += 128) {
        float acc = 0.f;
        #pragma unroll 8
        for (int d = 0; d < 128; d++)
            acc = fmaf(r[d], W[(size_t)(h * 128 + d) * 1024 + e], acc);
        M[(size_t)row * 1024 + e] = acc;
    }
    if (tid == 0) {
        float acc = 0.f;
        for (int d = 0; d < 128; d++) acc = fmaf(r[d], bb[h * 128 + d], acc);
        pb[row] = acc;
    }
}

// ---------------- phi from fused P --------------------------------------------
__global__ __launch_bounds__(256) void phi_sin(
    const float* __restrict__ P, float* __restrict__ PQ, float* __restrict__ PK)
{
    size_t idx = (size_t)blockIdx.x * 256 + threadIdx.x;
    size_t m = idx >> 9;
    int j = (int)(idx & 511);
    int h = j >> 6, kk = j & 63;
    size_t ob = m * 1024 + (h << 7) + kk;
    float s, cc;
    sincosf(P[m * 1024 + j], &s, &cc);
    PQ[ob]      = s  * 0.125f;
    PQ[ob + 64] = cc * 0.125f;
    sincosf(P[m * 1024 + 512 + j], &s, &cc);
    PK[ob]      = s  * 0.125f;
    PK[ob + 64] = cc * 0.125f;
}

// ---------------- split fp32 -> fp16 x3 concat (round-6 verified) -------------
__global__ __launch_bounds__(256) void split3h_kernel(
    const float* __restrict__ X, __half* __restrict__ O, int midIsLo, float scale)
{
    size_t idx = (size_t)blockIdx.x * 256 + threadIdx.x;
    size_t m = idx >> 8;
    int kq = (int)(idx & 255) << 2;
    float4 v = *(const float4*)(X + m * 1024 + kq);
    float f[4] = {v.x * scale, v.y * scale, v.z * scale, v.w * scale};
    __half h[4], l[4];
    #pragma unroll
    for (int i = 0; i < 4; i++) {
        h[i] = __float2half(f[i]);
        l[i] = __float2half(f[i] - __half2float(h[i]));
    }
    __half2 hp0 = __halves2half2(h[0], h[1]);
    __half2 hp1 = __halves2half2(h[2], h[3]);
    __half2 lp0 = __halves2half2(l[0], l[1]);
    __half2 lp1 = __halves2half2(l[2], l[3]);
    __half* o = O + m * K3 + kq;
    ((__half2*)o)[0] = hp0;
    ((__half2*)o)[1] = hp1;
    ((__half2*)(o + 1024))[0] = midIsLo ? lp0 : hp0;
    ((__half2*)(o + 1024))[1] = midIsLo ? lp1 : hp1;
    ((__half2*)(o + 2048))[0] = midIsLo ? hp0 : lp0;
    ((__half2*)(o + 2048))[1] = midIsLo ? hp1 : lp1;
}

// ---------------- split fp32 -> bf16 x3 concat (round-6 verified) -------------
__global__ __launch_bounds__(256) void split3b_kernel(
    const float* __restrict__ X, __nv_bfloat16* __restrict__ O, int midIsLo)
{
    size_t idx = (size_t)blockIdx.x * 256 + threadIdx.x;
    size_t m = idx >> 8;
    int kq = (int)(idx & 255) << 2;
    float4 v = *(const float4*)(X + m * 1024 + kq);
    float f[4] = {v.x, v.y, v.z, v.w};
    __nv_bfloat16 h[4], l[4];
    #pragma unroll
    for (int i = 0; i < 4; i++) {
        h[i] = __float2bfloat16(f[i]);
        l[i] = __float2bfloat16(f[i] - __bfloat162float(h[i]));
    }
    __nv_bfloat162 hp0 = __halves2bfloat162(h[0], h[1]);
    __nv_bfloat162 hp1 = __halves2bfloat162(h[2], h[3]);
    __nv_bfloat162 lp0 = __halves2bfloat162(l[0], l[1]);
    __nv_bfloat162 lp1 = __halves2bfloat162(l[2], l[3]);
    __nv_bfloat16* o = O + m * K3 + kq;
    ((__nv_bfloat162*)o)[0] = hp0;
    ((__nv_bfloat162*)o)[1] = hp1;
    ((__nv_bfloat162*)(o + 1024))[0] = midIsLo ? lp0 : hp0;
    ((__nv_bfloat162*)(o + 1024))[1] = midIsLo ? lp1 : hp1;
    ((__nv_bfloat162*)(o + 2048))[0] = midIsLo ? hp0 : lp0;
    ((__nv_bfloat162*)(o + 2048))[1] = midIsLo ? hp1 : lp1;
}

// ---------------- HMMA GEMM: C = (A . W^T) * outScale + bias ------------------
template<bool FP16, int KTOT>
__global__ __launch_bounds__(256) void gemm_hmma(
    const void* __restrict__ A3v, const void* __restrict__ W3v,
    const float* __restrict__ bias, float* __restrict__ C, float outScale)
{
    constexpr int NCHUNK = KTOT / 64;
    constexpr int ROWB   = KTOT * 2;
    extern __shared__ __align__(128) char smem[];
    const uint32_t sb = smem_u32(smem);
    const int tid  = threadIdx.x;
    const int lane = tid & 31;
    const int wid  = tid >> 5;
    const int m0 = blockIdx.y << 7;
    const int n0 = blockIdx.x << 7;
    const int wm = (wid >> 1) << 5;
    const int wn = (wid & 1) << 6;

    const char* Abase = (const char*)A3v + (size_t)m0 * ROWB;
    const char* Bbase = (const char*)W3v + (size_t)n0 * ROWB;

    const int lrow = tid >> 1;
    const int lc0  = (tid & 1) << 2;
    auto load_stage = [&](int chunk, int st) {
        const size_t gcol = (size_t)(chunk << 7);
        const uint32_t sa = sb + st * STAGE_B;
        #pragma unroll
        for (int c = 0; c < 4; c++) {
            int ch = lc0 + c;
            uint32_t soff = (lrow << 7) + (((ch ^ (lrow & 7))) << 4);
            cp16(sa + soff,         Abase + (size_t)lrow * ROWB + gcol + (ch << 4));
            cp16(sa + 16384 + soff, Bbase + (size_t)lrow * ROWB + gcol + (ch << 4));
        }
    };

    #pragma unroll
    for (int s = 0; s < NSTAGE; s++) {
        load_stage(s, s);
        asm volatile("cp.async.commit_group;" ::: "memory");
    }

    const int amln = wm + (lane & 15);
    const int acb  = (lane >> 4) << 4;
    const int asw  = (amln & 7) << 4;
    const int bnln = wn + (lane & 7) + ((lane & 16) >> 1);
    const int bcb  = (lane & 8) << 1;
    const int bsw  = (lane & 7) << 4;

    float acc[2][8][4] = {};

    for (int i = 0; i < NCHUNK; i++) {
        asm volatile("cp.async.wait_group %0;" :: "n"(NSTAGE - 1) : "memory");
        __syncthreads();
        const int st = i % NSTAGE;
        const uint32_t sa = sb + st * STAGE_B;
        const uint32_t sbB = sa + 16384;
        #pragma unroll
        for (int ks = 0; ks < 4; ks++) {
            uint32_t a[2][4];
            #pragma unroll
            for (int mi = 0; mi < 2; mi++) {
                uint32_t addr = sa + ((amln + (mi << 4)) << 7)
                              + (((ks << 5) + acb) ^ asw);
                ldm_x4(a[mi][0], a[mi][1], a[mi][2], a[mi][3], addr);
            }
            #pragma unroll
            for (int njp = 0; njp < 4; njp++) {
                uint32_t q0, q1, q2, q3;
                uint32_t addr = sbB + ((bnln + (njp << 4)) << 7)
                              + (((ks << 5) + bcb) ^ bsw);
                ldm_x4(q0, q1, q2, q3, addr);
                if (FP16) {
                    mma_f16(acc[0][2*njp],     a[0], q0, q1);
                    mma_f16(acc[0][2*njp + 1], a[0], q2, q3);
                    mma_f16(acc[1][2*njp],     a[1], q0, q1);
                    mma_f16(acc[1][2*njp + 1], a[1], q2, q3);
                } else {
                    mma_bf16(acc[0][2*njp],     a[0], q0, q1);
                    mma_bf16(acc[0][2*njp + 1], a[0], q2, q3);
                    mma_bf16(acc[1][2*njp],     a[1], q0, q1);
                    mma_bf16(acc[1][2*njp + 1], a[1], q2, q3);
                }
            }
        }
        __syncthreads();
        if (i + NSTAGE < NCHUNK) load_stage(i + NSTAGE, st);
        asm volatile("cp.async.commit_group;" ::: "memory");
    }

    const int rbase = m0 + wm + (lane >> 2);
    const int cbase = n0 + wn + ((lane & 3) << 1);
    #pragma unroll
    for (int mi = 0; mi < 2; mi++) {
        #pragma unroll
        for (int nj = 0; nj < 8; nj++) {
            int col = cbase + (nj << 3);
            float b0 = bias[col], b1 = bias[col + 1];
            float* p0 = C + (size_t)(rbase + (mi << 4)) * 1024 + col;
            float* p1 = p0 + 8 * 1024;
            float2 v0 = {acc[mi][nj][0] * outScale + b0, acc[mi][nj][1] * outScale + b1};
            float2 v1 = {acc[mi][nj][2] * outScale + b0, acc[mi][nj][3] * outScale + b1};
            *(float2*)p0 = v0;
            *(float2*)p1 = v1;
        }
    }
}

// ---------------- fp32 SGEMM: C[M,N] = A[M,Kd] * B[N,Kd]^T + bias[N] -------
__global__ __launch_bounds__(256) void sgemm_nt_bias(
    const float* __restrict__ A, const float* __restrict__ Bm,
    const float* __restrict__ bias, float* __restrict__ C,
    int M, int N, int Kd)
{
    __shared__ float As[16][128];
    __shared__ float Bs[16][128];
    const int bm = blockIdx.y * 128;
    const int bn = blockIdx.x * 128;
    const int tid = threadIdx.x;
    const int t0 = (tid >> 4) << 3;
    const int n0 = (tid & 15) << 3;
    const int lr = tid >> 2;
    const int lc = (tid & 3) << 2;
    const float* Ap = A + (size_t)(bm + lr) * Kd + lc;
    const float* Bp = Bm + (size_t)(bn + lr) * Kd + lc;
    const size_t half = (size_t)64 * Kd;

    float4 a0 = *(const float4*)(Ap);
    float4 a1 = *(const float4*)(Ap + half);
    float4 b0 = *(const float4*)(Bp);
    float4 b1 = *(const float4*)(Bp + half);

    float acc[8][8] = {};
    for (int k0 = 0; k0 < Kd; k0 += 16) {
        As[lc+0][lr]    = a0.x; As[lc+1][lr]    = a0.y; As[lc+2][lr]    = a0.z; As[lc+3][lr]    = a0.w;
        As[lc+0][lr+64] = a1.x; As[lc+1][lr+64] = a1.y; As[lc+2][lr+64] = a1.z; As[lc+3][lr+64] = a1.w;
        Bs[lc+0][lr]    = b0.x; Bs[lc+1][lr]    = b0.y; Bs[lc+2][lr]    = b0.z; Bs[lc+3][lr]    = b0.w;
        Bs[lc+0][lr+64] = b1.x; Bs[lc+1][lr+64] = b1.y; Bs[lc+2][lr+64] = b1.z; Bs[lc+3][lr+64] = b1.w;
        __syncthreads();
        if (k0 + 16 < Kd) {
            a0 = *(const float4*)(Ap + k0 + 16);
            a1 = *(const float4*)(Ap + k0 + 16 + half);
            b0 = *(const float4*)(Bp + k0 + 16);
            b1 = *(const float4*)(Bp + k0 + 16 + half);
        }
        #pragma unroll
        for (int kk = 0; kk < 16; kk++) {
            float4 x0 = *(const float4*)&As[kk][t0];
            float4 x1 = *(const float4*)&As[kk][t0+4];
            float4 y0 = *(const float4*)&Bs[kk][n0];
            float4 y1 = *(const float4*)&Bs[kk][n0+4];
            float ar[8] = {x0.x,x0.y,x0.z,x0.w,x1.x,x1.y,x1.z,x1.w};
            float br[8] = {y0.x,y0.y,y0.z,y0.w,y1.x,y1.y,y1.z,y1.w};
            #pragma unroll
            for (int i = 0; i < 8; i++)
                #pragma unroll
                for (int j = 0; j < 8; j++)
                    acc[i][j] = fmaf(ar[i], br[j], acc[i][j]);
        }
        __syncthreads();
    }
    float bb[8];
    #pragma unroll
    for (int j = 0; j < 8; j++) bb[j] = bias[bn + n0 + j];
    #pragma unroll
    for (int i = 0; i < 8; i++) {
        float* Cp = C + (size_t)(bm + t0 + i) * N + bn + n0;
        float4 o;
        o.x = acc[i][0]+bb[0]; o.y = acc[i][1]+bb[1]; o.z = acc[i][2]+bb[2]; o.w = acc[i][3]+bb[3];
        *(float4*)Cp = o;
        o.x = acc[i][4]+bb[4]; o.y = acc[i][5]+bb[5]; o.z = acc[i][6]+bb[6]; o.w = acc[i][7]+bb[7];
        *(float4*)(Cp + 4) = o;
    }
}

// ---------------- per-chunk state + fused z -------------------------------------
__global__ __launch_bounds__(256) void chunk_state_kernel(
    const float* __restrict__ PK, const float* __restrict__ V,
    float* __restrict__ S, float* __restrict__ Z)
{
    __shared__ float as[16][128];
    __shared__ float bs[16][128];
    const int c = blockIdx.x, bh = blockIdx.y;
    const int b = bh >> 3, h = bh & 7;
    const int tid = threadIdx.x;
    const int t0 = (tid >> 4) << 3;
    const int n0 = (tid & 15) << 3;
    float acc[8][8] = {};
    float zacc = 0.f;

    for (int s0 = 0; s0 < CH; s0 += 16) {
        #pragma unroll
        for (int it = 0; it < 2; it++) {
            int idx = tid + (it << 8);
            int r  = idx >> 5;
            int c4 = (idx & 31) << 2;
            size_t grow = ((size_t)(c * CH + s0 + r) * B_ + b) * E_ + h * D_;
            *(float4*)&as[r][c4] = *(const float4*)(PK + grow + c4);
            *(float4*)&bs[r][c4] = *(const float4*)(V  + grow + c4);
        }
        __syncthreads();
        if (tid < 128) {
            float za = 0.f;
            #pragma unroll
            for (int ss = 0; ss < 16; ss++) za += as[ss][tid];
            zacc += za;
        }
        #pragma unroll
        for (int ss = 0; ss < 16; ss++) {
            float4 x0 = *(const float4*)&as[ss][t0];
            float4 x1 = *(const float4*)&as[ss][t0+4];
            float4 y0 = *(const float4*)&bs[ss][n0];
            float4 y1 = *(const float4*)&bs[ss][n0+4];
            float ar[8] = {x0.x,x0.y,x0.z,x0.w,x1.x,x1.y,x1.z,x1.w};
            float br[8] = {y0.x,y0.y,y0.z,y0.w,y1.x,y1.y,y1.z,y1.w};
            #pragma unroll
            for (int i = 0; i < 8; i++)
                #pragma unroll
                for (int j = 0; j < 8; j++)
                    acc[i][j] = fmaf(ar[i], br[j], acc[i][j]);
        }
        __syncthreads();
    }
    float* Sp = S + ((size_t)c * BHN + bh) * (K2 * D_);
    #pragma unroll
    for (int i = 0; i < 8; i++) {
        float4 o;
        o.x = acc[i][0]; o.y = acc[i][1]; o.z = acc[i][2]; o.w = acc[i][3];
        *(float4*)(Sp + (size_t)(t0 + i) * D_ + n0) = o;
        o.x = acc[i][4]; o.y = acc[i][5]; o.z = acc[i][6]; o.w = acc[i][7];
        *(float4*)(Sp + (size_t)(t0 + i) * D_ + n0 + 4) = o;
    }
    if (tid < 128)
        Z[((size_t)c * BHN + bh) * K2 + tid] = zacc;
}

__global__ void prefix_S_kernel(float* __restrict__ S)
{
    const int bh = blockIdx.x;
    const int e  = blockIdx.y * 256 + threadIdx.x;
    float acc = 0.f;
    for (int c = 0; c < NC; c++) {
        size_t idx = ((size_t)c * BHN + bh) * (K2 * D_) + e;
        float t = S[idx]; S[idx] = acc; acc += t;
    }
}

__global__ void prefix_z_kernel(float* __restrict__ Z)
{
    const int bh = blockIdx.x;
    const int k  = threadIdx.x;
    float acc = 0.f;
    for (int c = 0; c < NC; c++) {
        size_t idx = ((size_t)c * BHN + bh) * K2 + k;
        float t = Z[idx]; Z[idx] = acc; acc += t;
    }
}

// ---------------- RFA output; writes attn directly as bf16x3 split --------------
#define RFA_SMEM ((2*128*132 + 16*132) * 4)
__global__ __launch_bounds__(256) void rfa_out_kernel(
    const float* __restrict__ PQ, const float* __restrict__ PK,
    const float* __restrict__ V,  const float* __restrict__ S,
    const float* __restrict__ Z,  __nv_bfloat16* __restrict__ A3)
{
    extern __shared__ float sm[];
    float* Qs = sm;
    float* Ss = sm + 128 * 132;
    float* Bs = sm + 2 * 128 * 132;

    const int c = blockIdx.x, bh = blockIdx.y;
    const int b = bh >> 3, h = bh & 7;
    const int tid = threadIdx.x;
    const int t0 = (tid >> 4) << 3;
    const int n0 = (tid & 15) << 3;

    #pragma unroll
    for (int it = 0; it < 16; it++) {
        int idx = tid + (it << 8);
        int r  = idx >> 5;
        int c4 = (idx & 31) << 2;
        size_t grow = ((size_t)(c * CH + r) * B_ + b) * E_ + h * K2;
        float4 vq = *(const float4*)(PQ + grow + c4);
        Qs[(c4+0)*132 + r] = vq.x; Qs[(c4+1)*132 + r] = vq.y;
        Qs[(c4+2)*132 + r] = vq.z; Qs[(c4+3)*132 + r] = vq.w;
        float4 vk = *(const float4*)(PK + grow + c4);
        Ss[(c4+0)*132 + r] = vk.x; Ss[(c4+1)*132 + r] = vk.y;
        Ss[(c4+2)*132 + r] = vk.z; Ss[(c4+3)*132 + r] = vk.w;
    }
    __syncthreads();

    float sc[8][8] = {};
    #pragma unroll
    for (int kk = 0; kk < K2; kk++) {
        float4 x0 = *(const float4*)&Qs[kk*132 + t0];
        float4 x1 = *(const float4*)&Qs[kk*132 + t0 + 4];
        float4 y0 = *(const float4*)&Ss[kk*132 + n0];
        float4 y1 = *(const float4*)&Ss[kk*132 + n0 + 4];
        float ar[8] = {x0.x,x0.y,x0.z,x0.w,x1.x,x1.y,x1.z,x1.w};
        float br[8] = {y0.x,y0.y,y0.z,y0.w,y1.x,y1.y,y1.z,y1.w};
        #pragma unroll
        for (int i = 0; i < 8; i++)
            #pragma unroll
            for (int j = 0; j < 8; j++)
                sc[i][j] = fmaf(ar[i], br[j], sc[i][j]);
    }
    __syncthreads();
    #pragma unroll
    for (int j = 0; j < 8; j++)
        #pragma unroll
        for (int i = 0; i < 8; i++)
            Ss[(size_t)(n0 + j) * 132 + (t0 + i)] = (n0 + j <= t0 + i) ? sc[i][j] : 0.0f;
    __syncthreads();

    float acc[8][8] = {};
    float dacc[8] = {};
    const float* Sp = S + ((size_t)c * BHN + bh) * (K2 * D_);
    const float* zp = Z + ((size_t)c * BHN + bh) * K2;
    for (int kt = 0; kt < 16; kt++) {
        const int rbase = kt << 4;
        #pragma unroll
        for (int it = 0; it < 2; it++) {
            int idx = tid + (it << 8);
            int r  = idx >> 5;
            int c4 = (idx & 31) << 2;
            int rr = rbase + r;
            float4 vv;
            if (rr < 128)
                vv = *(const float4*)(V + ((size_t)(c * CH + rr) * B_ + b) * E_ + h * D_ + c4);
            else
                vv = *(const float4*)(Sp + (size_t)(rr - 128) * D_ + c4);
            *(float4*)&Bs[r * 132 + c4] = vv;
        }
        if (tid < 16) {
            int rr = rbase + tid;
            Bs[tid * 132 + 128] = (rr < 128) ? 1.0f : zp[rr - 128];
        }
        __syncthreads();
        const float* Aop = (rbase < 128) ? (Ss + (size_t)rbase * 132)
                                         : (Qs + (size_t)(rbase - 128) * 132);
        #pragma unroll
        for (int ss = 0; ss < 16; ss++) {
            const float* arow = Aop + (size_t)ss * 132;
            float4 x0 = *(const float4*)(arow + t0);
            float4 x1 = *(const float4*)(arow + t0 + 4);
            float ar[8] = {x0.x,x0.y,x0.z,x0.w,x1.x,x1.y,x1.z,x1.w};
            float4 y0 = *(const float4*)&Bs[ss * 132 + n0];
            float4 y1 = *(const float4*)&Bs[ss * 132 + n0 + 4];
            float br[8] = {y0.x,y0.y,y0.z,y0.w,y1.x,y1.y,y1.z,y1.w};
            float bv = Bs[ss * 132 + 128];
            #pragma unroll
            for (int i = 0; i < 8; i++) {
                dacc[i] = fmaf(ar[i], bv, dacc[i]);
                #pragma unroll
                for (int j = 0; j < 8; j++)
                    acc[i][j] = fmaf(ar[i], br[j], acc[i][j]);
            }
        }
        __syncthreads();
    }

    // epilogue: out = num/den, emitted directly as bf16x3 [hi|lo|hi] rows of a3
    #pragma unroll
    for (int i = 0; i < 8; i++) {
        float inv = 1.0f / fmaxf(dacc[i], EPSV);
        size_t m = (size_t)(c * CH + t0 + i) * B_ + b;
        __nv_bfloat16* o = A3 + m * K3 + h * D_ + n0;
        __nv_bfloat16 hh[8], ll[8];
        #pragma unroll
        for (int j = 0; j < 8; j++) {
            float ov = acc[i][j] * inv;
            hh[j] = __float2bfloat16(ov);
            ll[j] = __float2bfloat16(ov - __bfloat162float(hh[j]));
        }
        #pragma unroll
        for (int j = 0; j < 4; j++) {
            __nv_bfloat162 hp = __halves2bfloat162(hh[2*j], hh[2*j+1]);
            __nv_bfloat162 lp = __halves2bfloat162(ll[2*j], ll[2*j+1]);
            ((__nv_bfloat162*)(o))[j]        = hp;   // seg0 = hi
            ((__nv_bfloat162*)(o + 1024))[j] = lp;   // seg1 = lo
            ((__nv_bfloat162*)(o + 2048))[j] = hp;   // seg2 = hi
        }
    }
}

// ---------------- launcher -----------------------------------------------------
extern "C" void kernel_launch(void* const* d_in, const int* in_sizes, int n_in,
                              void* d_out, int out_size)
{
    const float* x   = (const float*)d_in[0];
    const float* rm  = (const float*)d_in[1];
    const float* Wq  = (const float*)d_in[2];
    const float* bq  = (const float*)d_in[3];
    const float* Wk  = (const float*)d_in[4];
    const float* bk  = (const float*)d_in[5];
    const float* Wv  = (const float*)d_in[6];
    const float* bv  = (const float*)d_in[7];
    const float* Wo  = (const float*)d_in[8];
    const float* bo  = (const float*)d_in[9];
    const float* sig = (const float*)d_in[10];
    float* out = (float*)d_out;

    float *P, *v, *pq, *pk, *S, *z, *M, *pb;
    __half *a3, *wv3, *wo3;
    cudaGetSymbolAddress((void**)&P,    g_P);
    cudaGetSymbolAddress((void**)&v,    g_v);
    cudaGetSymbolAddress((void**)&pq,   g_pq);
    cudaGetSymbolAddress((void**)&pk,   g_pk);
    cudaGetSymbolAddress((void**)&S,    g_S);
    cudaGetSymbolAddress((void**)&z,    g_z);
    cudaGetSymbolAddress((void**)&M,    g_M);
    cudaGetSymbolAddress((void**)&pb,   g_pb);
    cudaGetSymbolAddress((void**)&a3,   g_a3);
    cudaGetSymbolAddress((void**)&wv3,  g_wv3);
    cudaGetSymbolAddress((void**)&wo3,  g_wo3);

    cudaFuncSetAttribute(rfa_out_kernel,
                         cudaFuncAttributeMaxDynamicSharedMemorySize, RFA_SMEM);
    cudaFuncSetAttribute((const void*)gemm_hmma<true, 3072>,
                         cudaFuncAttributeMaxDynamicSharedMemorySize, GEMM_SMEM);
    cudaFuncSetAttribute((const void*)gemm_hmma<false, 3072>,
                         cudaFuncAttributeMaxDynamicSharedMemorySize, GEMM_SMEM);

    const float invW = 1.0f / WSCALE;
    dim3 ghmma(E_ / 128, MR / 128);

    // fork a second stream for the (independent) v path
    cudaStream_t s1;
    cudaStreamCreateWithFlags(&s1, cudaStreamNonBlocking);
    cudaEvent_t e1, e2;
    cudaEventCreateWithFlags(&e1, cudaEventDisableTiming);
    cudaEventCreateWithFlags(&e2, cudaEventDisableTiming);

    // --- main stream: fused q/k matrix then fp32 P GEMM (den-critical) ---
    prep_M<<<1024, 128>>>(rm, sig, Wq, Wk, bq, bk, M, pb);
    cudaEventRecord(e1, 0);
    cudaStreamWaitEvent(s1, e1, 0);

    // --- stream 1: v path (splits + fp16x3 HMMA) + Wo split, parallel to P ---
    split3h_kernel<<<MR, 256, 0, s1>>>(x, a3, 1, 1.0f);
    split3h_kernel<<<1024, 256, 0, s1>>>(Wv, wv3, 0, WSCALE);
    gemm_hmma<true, 3072><<<ghmma, 256, GEMM_SMEM, s1>>>(a3, wv3, bv, v, invW);
    split3b_kernel<<<1024, 256, 0, s1>>>(Wo, (__nv_bfloat16*)wo3, 0);
    cudaEventRecord(e2, s1);

    // --- main stream continues: P (fp32), phi ---
    sgemm_nt_bias<<<dim3(E_ / 128, MR / 128), 256>>>(x, M, pb, P, MR, 1024, 1024);
    phi_sin<<<MR * 2, 256>>>(P, pq, pk);

    // join: chunk_state needs v from s1
    cudaStreamWaitEvent(0, e2, 0);

    dim3 gcs(NC, BHN);
    chunk_state_kernel<<<gcs, 256>>>(pk, v, S, z);
    prefix_S_kernel<<<dim3(BHN, 64), 256>>>(S);
    prefix_z_kernel<<<BHN, 128>>>(z);
    rfa_out_kernel<<<gcs, 256, RFA_SMEM>>>(pq, pk, v, S, z, (__nv_bfloat16*)a3);

    // O projection: bf16x3 HMMA (measured-safe), input already split by rfa_out
    gemm_hmma<false, 3072><<<ghmma, 256, GEMM_SMEM>>>(a3, wo3, bo, out, 1.0f);
}

// round 10
// speedup vs baseline: 1.8099x; 1.0539x over previous
#include <cuda_runtime.h>
#include <cuda_bf16.h>
#include <cuda_fp16.h>
#include <cstdint>

#define T_    4096
#define B_    8
#define E_    1024
#define H_    8
#define D_    128
#define KP    64
#define K2    128
#define CH    128
#define NC    32
#define MR    32768
#define BHN   64
#define EPSV  1e-6f

#define K3        3072
#define NSTAGE    3
#define STAGE_B   32768
#define GEMM_SMEM (NSTAGE * STAGE_B)   // 96KB
#define WSCALE    1024.0f

// ---------------- scratch ---------------------------------------------------
__device__ float g_v[33554432];
__device__ float g_pq[33554432];
__device__ float g_pk[33554432];
__device__ float g_S[33554432];
__device__ float g_z[262144];
__device__ float g_M[1048576];       // fused q/k projection matrix
__device__ float g_pb[1024];
__device__ __half g_a3[100663296];   // [MR][3072] x fp16x3, later attn bf16x3 (reuse)
__device__ __half g_wv3[3145728];    // Wv fp16x3
__device__ __half g_wo3[3145728];    // Wo bf16x3 (bits in half storage)

// ---------------- PTX helpers -----------------------------------------------
__device__ __forceinline__ uint32_t smem_u32(const void* p) {
    uint32_t a;
    asm("{ .reg .u64 t; cvta.to.shared.u64 t, %1; cvt.u32.u64 %0, t; }"
        : "=r"(a) : "l"(p));
    return a;
}
__device__ __forceinline__ void cp16(uint32_t dst, const void* src) {
    asm volatile("cp.async.cg.shared.global [%0], [%1], 16;" :: "r"(dst), "l"(src));
}
__device__ __forceinline__ void ldm_x4(uint32_t& r0, uint32_t& r1,
                                       uint32_t& r2, uint32_t& r3, uint32_t addr) {
    asm volatile("ldmatrix.sync.aligned.m8n8.x4.shared.b16 {%0,%1,%2,%3}, [%4];"
                 : "=r"(r0), "=r"(r1), "=r"(r2), "=r"(r3) : "r"(addr));
}
__device__ __forceinline__ void mma_f16(float* c, const uint32_t* a,
                                        uint32_t b0, uint32_t b1) {
    asm volatile(
        "mma.sync.aligned.m16n8k16.row.col.f32.f16.f16.f32 "
        "{%0,%1,%2,%3}, {%4,%5,%6,%7}, {%8,%9}, {%0,%1,%2,%3};"
        : "+f"(c[0]), "+f"(c[1]), "+f"(c[2]), "+f"(c[3])
        : "r"(a[0]), "r"(a[1]), "r"(a[2]), "r"(a[3]), "r"(b0), "r"(b1));
}
__device__ __forceinline__ void mma_bf16(float* c, const uint32_t* a,
                                         uint32_t b0, uint32_t b1) {
    asm volatile(
        "mma.sync.aligned.m16n8k16.row.col.f32.bf16.bf16.f32 "
        "{%0,%1,%2,%3}, {%4,%5,%6,%7}, {%8,%9}, {%0,%1,%2,%3};"
        : "+f"(c[0]), "+f"(c[1]), "+f"(c[2]), "+f"(c[3])
        : "r"(a[0]), "r"(a[1]), "r"(a[2]), "r"(a[3]), "r"(b0), "r"(b1));
}

// ---------------- prep: fused q/k projection matrix + bias -------------------
__global__ __launch_bounds__(128) void prep_M(
    const float* __restrict__ rm, const float* __restrict__ sig,
    const float* __restrict__ Wq, const float* __restrict__ Wk,
    const float* __restrict__ bq, const float* __restrict__ bk,
    float* __restrict__ M, float* __restrict__ pb)
{
    const int row = blockIdx.x;
    const int isK = row >> 9;
    const int h   = (row >> 6) & 7;
    const int kk  = row & 63;
    const float* W  = isK ? Wk : Wq;
    const float* bb = isK ? bk : bq;
    __shared__ float r[128];
    const int tid = threadIdx.x;
    const float c = 0.29730177875068026f;
    r[tid] = c * sig[h * 128 + tid] * rm[((size_t)(h * 64 + kk)) * 128 + tid];
    __syncthreads();
    for (int e = tid; e < 1024; e += 128) {
        float acc = 0.f;
        #pragma unroll 8
        for (int d = 0; d < 128; d++)
            acc = fmaf(r[d], W[(size_t)(h * 128 + d) * 1024 + e], acc);
        M[(size_t)row * 1024 + e] = acc;
    }
    if (tid == 0) {
        float acc = 0.f;
        for (int d = 0; d < 128; d++) acc = fmaf(r[d], bb[h * 128 + d], acc);
        pb[row] = acc;
    }
}

// ---------------- split fp32 -> fp16 x3 concat (round-6 verified) -------------
__global__ __launch_bounds__(256) void split3h_kernel(
    const float* __restrict__ X, __half* __restrict__ O, int midIsLo, float scale)
{
    size_t idx = (size_t)blockIdx.x * 256 + threadIdx.x;
    size_t m = idx >> 8;
    int kq = (int)(idx & 255) << 2;
    float4 v = *(const float4*)(X + m * 1024 + kq);
    float f[4] = {v.x * scale, v.y * scale, v.z * scale, v.w * scale};
    __half h[4], l[4];
    #pragma unroll
    for (int i = 0; i < 4; i++) {
        h[i] = __float2half(f[i]);
        l[i] = __float2half(f[i] - __half2float(h[i]));
    }
    __half2 hp0 = __halves2half2(h[0], h[1]);
    __half2 hp1 = __halves2half2(h[2], h[3]);
    __half2 lp0 = __halves2half2(l[0], l[1]);
    __half2 lp1 = __halves2half2(l[2], l[3]);
    __half* o = O + m * K3 + kq;
    ((__half2*)o)[0] = hp0;
    ((__half2*)o)[1] = hp1;
    ((__half2*)(o + 1024))[0] = midIsLo ? lp0 : hp0;
    ((__half2*)(o + 1024))[1] = midIsLo ? lp1 : hp1;
    ((__half2*)(o + 2048))[0] = midIsLo ? hp0 : lp0;
    ((__half2*)(o + 2048))[1] = midIsLo ? hp1 : lp1;
}

// ---------------- split fp32 -> bf16 x3 concat (round-6 verified) -------------
__global__ __launch_bounds__(256) void split3b_kernel(
    const float* __restrict__ X, __nv_bfloat16* __restrict__ O, int midIsLo)
{
    size_t idx = (size_t)blockIdx.x * 256 + threadIdx.x;
    size_t m = idx >> 8;
    int kq = (int)(idx & 255) << 2;
    float4 v = *(const float4*)(X + m * 1024 + kq);
    float f[4] = {v.x, v.y, v.z, v.w};
    __nv_bfloat16 h[4], l[4];
    #pragma unroll
    for (int i = 0; i < 4; i++) {
        h[i] = __float2bfloat16(f[i]);
        l[i] = __float2bfloat16(f[i] - __bfloat162float(h[i]));
    }
    __nv_bfloat162 hp0 = __halves2bfloat162(h[0], h[1]);
    __nv_bfloat162 hp1 = __halves2bfloat162(h[2], h[3]);
    __nv_bfloat162 lp0 = __halves2bfloat162(l[0], l[1]);
    __nv_bfloat162 lp1 = __halves2bfloat162(l[2], l[3]);
    __nv_bfloat16* o = O + m * K3 + kq;
    ((__nv_bfloat162*)o)[0] = hp0;
    ((__nv_bfloat162*)o)[1] = hp1;
    ((__nv_bfloat162*)(o + 1024))[0] = midIsLo ? lp0 : hp0;
    ((__nv_bfloat162*)(o + 1024))[1] = midIsLo ? lp1 : hp1;
    ((__nv_bfloat162*)(o + 2048))[0] = midIsLo ? hp0 : lp0;
    ((__nv_bfloat162*)(o + 2048))[1] = midIsLo ? hp1 : lp1;
}

// ---------------- HMMA GEMM: C = (A . W^T) * outScale + bias ------------------
template<bool FP16, int KTOT>
__global__ __launch_bounds__(256) void gemm_hmma(
    const void* __restrict__ A3v, const void* __restrict__ W3v,
    const float* __restrict__ bias, float* __restrict__ C, float outScale)
{
    constexpr int NCHUNK = KTOT / 64;
    constexpr int ROWB   = KTOT * 2;
    extern __shared__ __align__(128) char smem[];
    const uint32_t sb = smem_u32(smem);
    const int tid  = threadIdx.x;
    const int lane = tid & 31;
    const int wid  = tid >> 5;
    const int m0 = blockIdx.y << 7;
    const int n0 = blockIdx.x << 7;
    const int wm = (wid >> 1) << 5;
    const int wn = (wid & 1) << 6;

    const char* Abase = (const char*)A3v + (size_t)m0 * ROWB;
    const char* Bbase = (const char*)W3v + (size_t)n0 * ROWB;

    const int lrow = tid >> 1;
    const int lc0  = (tid & 1) << 2;
    auto load_stage = [&](int chunk, int st) {
        const size_t gcol = (size_t)(chunk << 7);
        const uint32_t sa = sb + st * STAGE_B;
        #pragma unroll
        for (int c = 0; c < 4; c++) {
            int ch = lc0 + c;
            uint32_t soff = (lrow << 7) + (((ch ^ (lrow & 7))) << 4);
            cp16(sa + soff,         Abase + (size_t)lrow * ROWB + gcol + (ch << 4));
            cp16(sa + 16384 + soff, Bbase + (size_t)lrow * ROWB + gcol + (ch << 4));
        }
    };

    #pragma unroll
    for (int s = 0; s < NSTAGE; s++) {
        load_stage(s, s);
        asm volatile("cp.async.commit_group;" ::: "memory");
    }

    const int amln = wm + (lane & 15);
    const int acb  = (lane >> 4) << 4;
    const int asw  = (amln & 7) << 4;
    const int bnln = wn + (lane & 7) + ((lane & 16) >> 1);
    const int bcb  = (lane & 8) << 1;
    const int bsw  = (lane & 7) << 4;

    float acc[2][8][4] = {};

    for (int i = 0; i < NCHUNK; i++) {
        asm volatile("cp.async.wait_group %0;" :: "n"(NSTAGE - 1) : "memory");
        __syncthreads();
        const int st = i % NSTAGE;
        const uint32_t sa = sb + st * STAGE_B;
        const uint32_t sbB = sa + 16384;
        #pragma unroll
        for (int ks = 0; ks < 4; ks++) {
            uint32_t a[2][4];
            #pragma unroll
            for (int mi = 0; mi < 2; mi++) {
                uint32_t addr = sa + ((amln + (mi << 4)) << 7)
                              + (((ks << 5) + acb) ^ asw);
                ldm_x4(a[mi][0], a[mi][1], a[mi][2], a[mi][3], addr);
            }
            #pragma unroll
            for (int njp = 0; njp < 4; njp++) {
                uint32_t q0, q1, q2, q3;
                uint32_t addr = sbB + ((bnln + (njp << 4)) << 7)
                              + (((ks << 5) + bcb) ^ bsw);
                ldm_x4(q0, q1, q2, q3, addr);
                if (FP16) {
                    mma_f16(acc[0][2*njp],     a[0], q0, q1);
                    mma_f16(acc[0][2*njp + 1], a[0], q2, q3);
                    mma_f16(acc[1][2*njp],     a[1], q0, q1);
                    mma_f16(acc[1][2*njp + 1], a[1], q2, q3);
                } else {
                    mma_bf16(acc[0][2*njp],     a[0], q0, q1);
                    mma_bf16(acc[0][2*njp + 1], a[0], q2, q3);
                    mma_bf16(acc[1][2*njp],     a[1], q0, q1);
                    mma_bf16(acc[1][2*njp + 1], a[1], q2, q3);
                }
            }
        }
        __syncthreads();
        if (i + NSTAGE < NCHUNK) load_stage(i + NSTAGE, st);
        asm volatile("cp.async.commit_group;" ::: "memory");
    }

    const int rbase = m0 + wm + (lane >> 2);
    const int cbase = n0 + wn + ((lane & 3) << 1);
    #pragma unroll
    for (int mi = 0; mi < 2; mi++) {
        #pragma unroll
        for (int nj = 0; nj < 8; nj++) {
            int col = cbase + (nj << 3);
            float b0 = bias[col], b1 = bias[col + 1];
            float* p0 = C + (size_t)(rbase + (mi << 4)) * 1024 + col;
            float* p1 = p0 + 8 * 1024;
            float2 v0 = {acc[mi][nj][0] * outScale + b0, acc[mi][nj][1] * outScale + b1};
            float2 v1 = {acc[mi][nj][2] * outScale + b0, acc[mi][nj][3] * outScale + b1};
            *(float2*)p0 = v0;
            *(float2*)p1 = v1;
        }
    }
}

// ---------------- fp32 SGEMM + fused phi: writes sin/cos directly -------------
// C-cols 0..511 -> PQ head/k slots; 512..1023 -> PK. Epilogue sincos is MUFU
// work that overlaps FFMA mainloop work of other warps/blocks.
__global__ __launch_bounds__(256) void sgemm_phi(
    const float* __restrict__ A, const float* __restrict__ Bm,
    const float* __restrict__ bias,
    float* __restrict__ PQ, float* __restrict__ PK, int Kd)
{
    __shared__ float As[16][128];
    __shared__ float Bs[16][128];
    const int bm = blockIdx.y * 128;
    const int bn = blockIdx.x * 128;
    const int tid = threadIdx.x;
    const int t0 = (tid >> 4) << 3;
    const int n0 = (tid & 15) << 3;
    const int lr = tid >> 2;
    const int lc = (tid & 3) << 2;
    const float* Ap = A + (size_t)(bm + lr) * Kd + lc;
    const float* Bp = Bm + (size_t)(bn + lr) * Kd + lc;
    const size_t half = (size_t)64 * Kd;

    float4 a0 = *(const float4*)(Ap);
    float4 a1 = *(const float4*)(Ap + half);
    float4 b0 = *(const float4*)(Bp);
    float4 b1 = *(const float4*)(Bp + half);

    float acc[8][8] = {};
    for (int k0 = 0; k0 < Kd; k0 += 16) {
        As[lc+0][lr]    = a0.x; As[lc+1][lr]    = a0.y; As[lc+2][lr]    = a0.z; As[lc+3][lr]    = a0.w;
        As[lc+0][lr+64] = a1.x; As[lc+1][lr+64] = a1.y; As[lc+2][lr+64] = a1.z; As[lc+3][lr+64] = a1.w;
        Bs[lc+0][lr]    = b0.x; Bs[lc+1][lr]    = b0.y; Bs[lc+2][lr]    = b0.z; Bs[lc+3][lr]    = b0.w;
        Bs[lc+0][lr+64] = b1.x; Bs[lc+1][lr+64] = b1.y; Bs[lc+2][lr+64] = b1.z; Bs[lc+3][lr+64] = b1.w;
        __syncthreads();
        if (k0 + 16 < Kd) {
            a0 = *(const float4*)(Ap + k0 + 16);
            a1 = *(const float4*)(Ap + k0 + 16 + half);
            b0 = *(const float4*)(Bp + k0 + 16);
            b1 = *(const float4*)(Bp + k0 + 16 + half);
        }
        #pragma unroll
        for (int kk = 0; kk < 16; kk++) {
            float4 x0 = *(const float4*)&As[kk][t0];
            float4 x1 = *(const float4*)&As[kk][t0+4];
            float4 y0 = *(const float4*)&Bs[kk][n0];
            float4 y1 = *(const float4*)&Bs[kk][n0+4];
            float ar[8] = {x0.x,x0.y,x0.z,x0.w,x1.x,x1.y,x1.z,x1.w};
            float br[8] = {y0.x,y0.y,y0.z,y0.w,y1.x,y1.y,y1.z,y1.w};
            #pragma unroll
            for (int i = 0; i < 8; i++)
                #pragma unroll
                for (int j = 0; j < 8; j++)
                    acc[i][j] = fmaf(ar[i], br[j], acc[i][j]);
        }
        __syncthreads();
    }

    // fused phi epilogue: col -> (head h, proj k) slot; sin at +0, cos at +64
    float bb[8];
    #pragma unroll
    for (int j = 0; j < 8; j++) bb[j] = bias[bn + n0 + j];
    const int colg = bn + n0;                 // tile never straddles 512 boundary
    float* OUTB = (colg < 512) ? PQ : PK;
    const int cc  = colg & 511;
    const int hh  = cc >> 6;
    const int kk0 = cc & 63;
    #pragma unroll
    for (int i = 0; i < 8; i++) {
        size_t base = (size_t)(bm + t0 + i) * 1024 + (hh << 7) + kk0;
        float sv[8], cv[8];
        #pragma unroll
        for (int j = 0; j < 8; j++) {
            float s, c;
            sincosf(acc[i][j] + bb[j], &s, &c);
            sv[j] = s * 0.125f;
            cv[j] = c * 0.125f;
        }
        float4 o;
        o.x=sv[0]; o.y=sv[1]; o.z=sv[2]; o.w=sv[3]; *(float4*)&OUTB[base]      = o;
        o.x=sv[4]; o.y=sv[5]; o.z=sv[6]; o.w=sv[7]; *(float4*)&OUTB[base + 4]  = o;
        o.x=cv[0]; o.y=cv[1]; o.z=cv[2]; o.w=cv[3]; *(float4*)&OUTB[base + 64] = o;
        o.x=cv[4]; o.y=cv[5]; o.z=cv[6]; o.w=cv[7]; *(float4*)&OUTB[base + 68] = o;
    }
}

// ---------------- per-chunk state + fused z -------------------------------------
__global__ __launch_bounds__(256) void chunk_state_kernel(
    const float* __restrict__ PK, const float* __restrict__ V,
    float* __restrict__ S, float* __restrict__ Z)
{
    __shared__ float as[16][128];
    __shared__ float bs[16][128];
    const int c = blockIdx.x, bh = blockIdx.y;
    const int b = bh >> 3, h = bh & 7;
    const int tid = threadIdx.x;
    const int t0 = (tid >> 4) << 3;
    const int n0 = (tid & 15) << 3;
    float acc[8][8] = {};
    float zacc = 0.f;

    for (int s0 = 0; s0 < CH; s0 += 16) {
        #pragma unroll
        for (int it = 0; it < 2; it++) {
            int idx = tid + (it << 8);
            int r  = idx >> 5;
            int c4 = (idx & 31) << 2;
            size_t grow = ((size_t)(c * CH + s0 + r) * B_ + b) * E_ + h * D_;
            *(float4*)&as[r][c4] = *(const float4*)(PK + grow + c4);
            *(float4*)&bs[r][c4] = *(const float4*)(V  + grow + c4);
        }
        __syncthreads();
        if (tid < 128) {
            float za = 0.f;
            #pragma unroll
            for (int ss = 0; ss < 16; ss++) za += as[ss][tid];
            zacc += za;
        }
        #pragma unroll
        for (int ss = 0; ss < 16; ss++) {
            float4 x0 = *(const float4*)&as[ss][t0];
            float4 x1 = *(const float4*)&as[ss][t0+4];
            float4 y0 = *(const float4*)&bs[ss][n0];
            float4 y1 = *(const float4*)&bs[ss][n0+4];
            float ar[8] = {x0.x,x0.y,x0.z,x0.w,x1.x,x1.y,x1.z,x1.w};
            float br[8] = {y0.x,y0.y,y0.z,y0.w,y1.x,y1.y,y1.z,y1.w};
            #pragma unroll
            for (int i = 0; i < 8; i++)
                #pragma unroll
                for (int j = 0; j < 8; j++)
                    acc[i][j] = fmaf(ar[i], br[j], acc[i][j]);
        }
        __syncthreads();
    }
    float* Sp = S + ((size_t)c * BHN + bh) * (K2 * D_);
    #pragma unroll
    for (int i = 0; i < 8; i++) {
        float4 o;
        o.x = acc[i][0]; o.y = acc[i][1]; o.z = acc[i][2]; o.w = acc[i][3];
        *(float4*)(Sp + (size_t)(t0 + i) * D_ + n0) = o;
        o.x = acc[i][4]; o.y = acc[i][5]; o.z = acc[i][6]; o.w = acc[i][7];
        *(float4*)(Sp + (size_t)(t0 + i) * D_ + n0 + 4) = o;
    }
    if (tid < 128)
        Z[((size_t)c * BHN + bh) * K2 + tid] = zacc;
}

__global__ void prefix_S_kernel(float* __restrict__ S)
{
    const int bh = blockIdx.x;
    const int e  = blockIdx.y * 256 + threadIdx.x;
    float acc = 0.f;
    for (int c = 0; c < NC; c++) {
        size_t idx = ((size_t)c * BHN + bh) * (K2 * D_) + e;
        float t = S[idx]; S[idx] = acc; acc += t;
    }
}

__global__ void prefix_z_kernel(float* __restrict__ Z)
{
    const int bh = blockIdx.x;
    const int k  = threadIdx.x;
    float acc = 0.f;
    for (int c = 0; c < NC; c++) {
        size_t idx = ((size_t)c * BHN + bh) * K2 + k;
        float t = Z[idx]; Z[idx] = acc; acc += t;
    }
}

// ---------------- RFA output (restructured for 2 CTAs/SM) -----------------------
// smem: scores 128x132 resident; Q/K streamed in 16-row transposed tiles.
// Phase1: scores = Q.K^T (k-tiled). Phase2: num/den GEMM over 256 reduction
// rows (scores|Q) x (V;S_prefix | 1;z). Emits attn directly as bf16x3.
#define RFA_SMEM ((128*132 + 2*16*132) * 4)   // 84480 B -> 2 CTAs/SM
__global__ __launch_bounds__(256) void rfa_out_kernel(
    const float* __restrict__ PQ, const float* __restrict__ PK,
    const float* __restrict__ V,  const float* __restrict__ S,
    const float* __restrict__ Z,  __nv_bfloat16* __restrict__ A3)
{
    extern __shared__ float sm[];
    float* SC = sm;                    // [s][t] masked scores (stride 132)
    float* TA = sm + 128 * 132;        // [16][132] transposed Q tile
    float* TB = TA + 16 * 132;         // [16][132] K tile (ph1) / B rows + den col (ph2)

    const int c = blockIdx.x, bh = blockIdx.y;
    const int b = bh >> 3, h = bh & 7;
    const int tid = threadIdx.x;
    const int t0 = (tid >> 4) << 3;
    const int n0 = (tid & 15) << 3;

    // ---- phase 1: scores[t][s], k-tiled by 16 ----
    float sc[8][8] = {};
    for (int kt = 0; kt < 8; kt++) {
        #pragma unroll
        for (int it = 0; it < 2; it++) {
            int idx = tid + (it << 8);        // 0..511
            int r  = idx >> 2;                // row 0..127
            int c4 = (idx & 3) << 2;          // k offset 0..12
            size_t grow = ((size_t)(c * CH + r) * B_ + b) * E_ + h * K2 + (kt << 4) + c4;
            float4 vq = *(const float4*)(PQ + grow);
            TA[(c4+0)*132 + r] = vq.x; TA[(c4+1)*132 + r] = vq.y;
            TA[(c4+2)*132 + r] = vq.z; TA[(c4+3)*132 + r] = vq.w;
            float4 vk = *(const float4*)(PK + grow);
            TB[(c4+0)*132 + r] = vk.x; TB[(c4+1)*132 + r] = vk.y;
            TB[(c4+2)*132 + r] = vk.z; TB[(c4+3)*132 + r] = vk.w;
        }
        __syncthreads();
        #pragma unroll
        for (int kk = 0; kk < 16; kk++) {
            float4 x0 = *(const float4*)&TA[kk*132 + t0];
            float4 x1 = *(const float4*)&TA[kk*132 + t0 + 4];
            float4 y0 = *(const float4*)&TB[kk*132 + n0];
            float4 y1 = *(const float4*)&TB[kk*132 + n0 + 4];
            float ar[8] = {x0.x,x0.y,x0.z,x0.w,x1.x,x1.y,x1.z,x1.w};
            float br[8] = {y0.x,y0.y,y0.z,y0.w,y1.x,y1.y,y1.z,y1.w};
            #pragma unroll
            for (int i = 0; i < 8; i++)
                #pragma unroll
                for (int j = 0; j < 8; j++)
                    sc[i][j] = fmaf(ar[i], br[j], sc[i][j]);
        }
        __syncthreads();
    }
    // masked transposed store: SC[s][t]
    #pragma unroll
    for (int j = 0; j < 8; j++)
        #pragma unroll
        for (int i = 0; i < 8; i++)
            SC[(size_t)(n0 + j) * 132 + (t0 + i)] = (n0 + j <= t0 + i) ? sc[i][j] : 0.0f;
    __syncthreads();

    // ---- phase 2: num/den over 256 reduction rows ----
    float acc[8][8] = {};
    float dacc[8] = {};
    const float* Sp = S + ((size_t)c * BHN + bh) * (K2 * D_);
    const float* zp = Z + ((size_t)c * BHN + bh) * K2;
    for (int kt = 0; kt < 16; kt++) {
        const int rbase = kt << 4;
        #pragma unroll
        for (int it = 0; it < 2; it++) {
            int idx = tid + (it << 8);
            int r  = idx >> 5;
            int c4 = (idx & 31) << 2;
            int rr = rbase + r;
            float4 vv;
            if (rr < 128)
                vv = *(const float4*)(V + ((size_t)(c * CH + rr) * B_ + b) * E_ + h * D_ + c4);
            else
                vv = *(const float4*)(Sp + (size_t)(rr - 128) * D_ + c4);
            *(float4*)&TB[r * 132 + c4] = vv;
        }
        if (tid < 16) {
            int rr = rbase + tid;
            TB[tid * 132 + 128] = (rr < 128) ? 1.0f : zp[rr - 128];
        }
        if (rbase >= 128) {
            // reload Q slice (k-rows rbase-128..+15) transposed into TA
            #pragma unroll
            for (int it = 0; it < 2; it++) {
                int idx = tid + (it << 8);
                int r  = idx >> 2;
                int c4 = (idx & 3) << 2;
                size_t grow = ((size_t)(c * CH + r) * B_ + b) * E_ + h * K2
                            + (rbase - 128) + c4;
                float4 vq = *(const float4*)(PQ + grow);
                TA[(c4+0)*132 + r] = vq.x; TA[(c4+1)*132 + r] = vq.y;
                TA[(c4+2)*132 + r] = vq.z; TA[(c4+3)*132 + r] = vq.w;
            }
        }
        __syncthreads();
        const float* Aop = (rbase < 128) ? (SC + (size_t)rbase * 132) : TA;
        #pragma unroll
        for (int ss = 0; ss < 16; ss++) {
            const float* arow = Aop + (size_t)ss * 132;
            float4 x0 = *(const float4*)(arow + t0);
            float4 x1 = *(const float4*)(arow + t0 + 4);
            float ar[8] = {x0.x,x0.y,x0.z,x0.w,x1.x,x1.y,x1.z,x1.w};
            float4 y0 = *(const float4*)&TB[ss * 132 + n0];
            float4 y1 = *(const float4*)&TB[ss * 132 + n0 + 4];
            float br[8] = {y0.x,y0.y,y0.z,y0.w,y1.x,y1.y,y1.z,y1.w};
            float bv = TB[ss * 132 + 128];
            #pragma unroll
            for (int i = 0; i < 8; i++) {
                dacc[i] = fmaf(ar[i], bv, dacc[i]);
                #pragma unroll
                for (int j = 0; j < 8; j++)
                    acc[i][j] = fmaf(ar[i], br[j], acc[i][j]);
            }
        }
        __syncthreads();
    }

    // epilogue: out = num/den, emitted directly as bf16x3 [hi|lo|hi] rows of a3
    #pragma unroll
    for (int i = 0; i < 8; i++) {
        float inv = 1.0f / fmaxf(dacc[i], EPSV);
        size_t m = (size_t)(c * CH + t0 + i) * B_ + b;
        __nv_bfloat16* o = A3 + m * K3 + h * D_ + n0;
        __nv_bfloat16 hh[8], ll[8];
        #pragma unroll
        for (int j = 0; j < 8; j++) {
            float ov = acc[i][j] * inv;
            hh[j] = __float2bfloat16(ov);
            ll[j] = __float2bfloat16(ov - __bfloat162float(hh[j]));
        }
        #pragma unroll
        for (int j = 0; j < 4; j++) {
            __nv_bfloat162 hp = __halves2bfloat162(hh[2*j], hh[2*j+1]);
            __nv_bfloat162 lp = __halves2bfloat162(ll[2*j], ll[2*j+1]);
            ((__nv_bfloat162*)(o))[j]        = hp;
            ((__nv_bfloat162*)(o + 1024))[j] = lp;
            ((__nv_bfloat162*)(o + 2048))[j] = hp;
        }
    }
}

// ---------------- launcher -----------------------------------------------------
extern "C" void kernel_launch(void* const* d_in, const int* in_sizes, int n_in,
                              void* d_out, int out_size)
{
    const float* x   = (const float*)d_in[0];
    const float* rm  = (const float*)d_in[1];
    const float* Wq  = (const float*)d_in[2];
    const float* bq  = (const float*)d_in[3];
    const float* Wk  = (const float*)d_in[4];
    const float* bk  = (const float*)d_in[5];
    const float* Wv  = (const float*)d_in[6];
    const float* bv  = (const float*)d_in[7];
    const float* Wo  = (const float*)d_in[8];
    const float* bo  = (const float*)d_in[9];
    const float* sig = (const float*)d_in[10];
    float* out = (float*)d_out;

    float *v, *pq, *pk, *S, *z, *M, *pb;
    __half *a3, *wv3, *wo3;
    cudaGetSymbolAddress((void**)&v,    g_v);
    cudaGetSymbolAddress((void**)&pq,   g_pq);
    cudaGetSymbolAddress((void**)&pk,   g_pk);
    cudaGetSymbolAddress((void**)&S,    g_S);
    cudaGetSymbolAddress((void**)&z,    g_z);
    cudaGetSymbolAddress((void**)&M,    g_M);
    cudaGetSymbolAddress((void**)&pb,   g_pb);
    cudaGetSymbolAddress((void**)&a3,   g_a3);
    cudaGetSymbolAddress((void**)&wv3,  g_wv3);
    cudaGetSymbolAddress((void**)&wo3,  g_wo3);

    cudaFuncSetAttribute(rfa_out_kernel,
                         cudaFuncAttributeMaxDynamicSharedMemorySize, RFA_SMEM);
    cudaFuncSetAttribute((const void*)gemm_hmma<true, 3072>,
                         cudaFuncAttributeMaxDynamicSharedMemorySize, GEMM_SMEM);
    cudaFuncSetAttribute((const void*)gemm_hmma<false, 3072>,
                         cudaFuncAttributeMaxDynamicSharedMemorySize, GEMM_SMEM);

    const float invW = 1.0f / WSCALE;
    dim3 ghmma(E_ / 128, MR / 128);

    // fork a second stream for the (independent) v path
    cudaStream_t s1;
    cudaStreamCreateWithFlags(&s1, cudaStreamNonBlocking);
    cudaEvent_t e1, e2;
    cudaEventCreateWithFlags(&e1, cudaEventDisableTiming);
    cudaEventCreateWithFlags(&e2, cudaEventDisableTiming);

    // --- main stream: fused q/k matrix then fp32 P GEMM + fused phi ---
    prep_M<<<1024, 128>>>(rm, sig, Wq, Wk, bq, bk, M, pb);
    cudaEventRecord(e1, 0);
    cudaStreamWaitEvent(s1, e1, 0);

    // --- stream 1: v path (splits + fp16x3 HMMA) + Wo split, parallel to P ---
    split3h_kernel<<<MR, 256, 0, s1>>>(x, a3, 1, 1.0f);
    split3h_kernel<<<1024, 256, 0, s1>>>(Wv, wv3, 0, WSCALE);
    gemm_hmma<true, 3072><<<ghmma, 256, GEMM_SMEM, s1>>>(a3, wv3, bv, v, invW);
    split3b_kernel<<<1024, 256, 0, s1>>>(Wo, (__nv_bfloat16*)wo3, 0);
    cudaEventRecord(e2, s1);

    // --- main stream: P GEMM with fused sincos epilogue -> pq/pk directly ---
    sgemm_phi<<<dim3(E_ / 128, MR / 128), 256>>>(x, M, pb, pq, pk, 1024);

    // join: chunk_state needs v from s1
    cudaStreamWaitEvent(0, e2, 0);

    dim3 gcs(NC, BHN);
    chunk_state_kernel<<<gcs, 256>>>(pk, v, S, z);
    prefix_S_kernel<<<dim3(BHN, 64), 256>>>(S);
    prefix_z_kernel<<<BHN, 128>>>(z);
    rfa_out_kernel<<<gcs, 256, RFA_SMEM>>>(pq, pk, v, S, z, (__nv_bfloat16*)a3);

    // O projection: bf16x3 HMMA (measured-safe), input already split by rfa_out
    gemm_hmma<false, 3072><<<ghmma, 256, GEMM_SMEM>>>(a3, wo3, bo, out, 1.0f);
}